// round 4
// baseline (speedup 1.0000x reference)
#include <cuda_runtime.h>
#include <math.h>

// Problem dims (fixed by reference)
#define Bsz  16
#define Ssz  512
#define Hsz  768
#define Lsz  12
#define NHsz 12
#define FFsz 3072
#define Dsz  64
#define TOK  (Bsz * Ssz)   // 8192 tokens

// ---------------- scratch (static device globals; allocation-free) ----------------
__device__ float g_x  [TOK * Hsz];
__device__ float g_q  [TOK * Hsz];
__device__ float g_k  [TOK * Hsz];
__device__ float g_v  [TOK * Hsz];
__device__ float g_ctx[TOK * Hsz];
__device__ float g_tmp[TOK * Hsz];
__device__ float g_ffn[TOK * FFsz];

// ---------------- block reductions ----------------
__device__ __forceinline__ float block_sum_256(float val, float* red) {
    #pragma unroll
    for (int o = 16; o > 0; o >>= 1) val += __shfl_xor_sync(0xffffffffu, val, o);
    if ((threadIdx.x & 31) == 0) red[threadIdx.x >> 5] = val;
    __syncthreads();
    float s = red[0];
    #pragma unroll
    for (int w = 1; w < 8; w++) s += red[w];
    __syncthreads();
    return s;
}

__device__ __forceinline__ float block_max_128(float val, float* red) {
    #pragma unroll
    for (int o = 16; o > 0; o >>= 1) val = fmaxf(val, __shfl_xor_sync(0xffffffffu, val, o));
    if ((threadIdx.x & 31) == 0) red[threadIdx.x >> 5] = val;
    __syncthreads();
    float m = fmaxf(fmaxf(red[0], red[1]), fmaxf(red[2], red[3]));
    __syncthreads();
    return m;
}

__device__ __forceinline__ float block_sum_128(float val, float* red) {
    #pragma unroll
    for (int o = 16; o > 0; o >>= 1) val += __shfl_xor_sync(0xffffffffu, val, o);
    if ((threadIdx.x & 31) == 0) red[threadIdx.x >> 5] = val;
    __syncthreads();
    float s = red[0] + red[1] + red[2] + red[3];
    __syncthreads();
    return s;
}

// ---------------- embeddings + LN + gaussian noise ----------------
__global__ void embed_kernel(const int* __restrict__ ids, const int* __restrict__ tts,
                             const float* __restrict__ we, const float* __restrict__ pe,
                             const float* __restrict__ te, const float* __restrict__ g,
                             const float* __restrict__ beta, const float* __restrict__ imp,
                             const float* __restrict__ noise, float* __restrict__ x)
{
    __shared__ float red[8];
    int tok = blockIdx.x;
    int s   = tok & (Ssz - 1);
    int tid = threadIdx.x;
    long id = ids[tok];
    long tt = tts[tok];
    float v[3];
    #pragma unroll
    for (int i = 0; i < 3; i++) {
        int hh = tid + i * 256;
        v[i] = we[(size_t)id * Hsz + hh] + pe[(size_t)s * Hsz + hh] + te[(size_t)tt * Hsz + hh];
    }
    float mu = block_sum_256(v[0] + v[1] + v[2], red) * (1.0f / Hsz);
    float d0 = v[0] - mu, d1 = v[1] - mu, d2 = v[2] - mu;
    float var = block_sum_256(d0 * d0 + d1 * d1 + d2 * d2, red) * (1.0f / Hsz);
    float rstd = rsqrtf(var + 1e-12f);
    float ip = imp[tok];
    float sg = 1.0f - ip;
    bool  nz = (ip != 0.0f);
    float dd[3] = {d0, d1, d2};
    #pragma unroll
    for (int i = 0; i < 3; i++) {
        int hh = tid + i * 256;
        float e = dd[i] * rstd * g[hh] + beta[hh];
        if (nz) e = e + noise[(size_t)tok * Hsz + hh] * sg * e;
        x[(size_t)tok * Hsz + hh] = e;
    }
}

// ---------------- residual add + LayerNorm (in-place on x) ----------------
__global__ void add_ln_kernel(float* __restrict__ x, const float* __restrict__ r,
                              const float* __restrict__ g, const float* __restrict__ beta)
{
    __shared__ float red[8];
    int tok = blockIdx.x, tid = threadIdx.x;
    size_t base = (size_t)tok * Hsz;
    float v[3];
    #pragma unroll
    for (int i = 0; i < 3; i++) {
        int hh = tid + i * 256;
        v[i] = x[base + hh] + r[base + hh];
    }
    float mu = block_sum_256(v[0] + v[1] + v[2], red) * (1.0f / Hsz);
    float d0 = v[0] - mu, d1 = v[1] - mu, d2 = v[2] - mu;
    float var = block_sum_256(d0 * d0 + d1 * d1 + d2 * d2, red) * (1.0f / Hsz);
    float rstd = rsqrtf(var + 1e-12f);
    float dd[3] = {d0, d1, d2};
    #pragma unroll
    for (int i = 0; i < 3; i++) {
        int hh = tid + i * 256;
        x[base + hh] = dd[i] * rstd * g[hh] + beta[hh];
    }
}

// ---------------- SGEMM: C = A[M,K] @ B[K,N] + bias, 128x128x8 tiles ----------------
// MODE 0: row-major out. MODE 1: gelu(exact) epilogue. MODE 2: scatter to [B,NH,S,D].
template <int MODE>
__global__ void __launch_bounds__(256, 2)
gemm128(const float* __restrict__ A, const float* __restrict__ Bm,
        const float* __restrict__ bias, float* __restrict__ C,
        int M, int N, int K)
{
    __shared__ float As[8][128];
    __shared__ float Bs[8][128];
    int tid = threadIdx.x;
    int tx = tid & 15, ty = tid >> 4;
    int bm = blockIdx.y * 128, bn = blockIdx.x * 128;

    int arow  = tid >> 1;         // 0..127
    int acol4 = (tid & 1) * 4;    // 0 or 4
    int brow  = tid >> 5;         // 0..7
    int bcol  = (tid & 31) * 4;   // 0..124

    float acc[8][8];
    #pragma unroll
    for (int i = 0; i < 8; i++)
        #pragma unroll
        for (int j = 0; j < 8; j++) acc[i][j] = 0.0f;

    for (int k0 = 0; k0 < K; k0 += 8) {
        float4 av = *(const float4*)(A + (size_t)(bm + arow) * K + k0 + acol4);
        As[acol4 + 0][arow] = av.x;
        As[acol4 + 1][arow] = av.y;
        As[acol4 + 2][arow] = av.z;
        As[acol4 + 3][arow] = av.w;
        *(float4*)&Bs[brow][bcol] = *(const float4*)(Bm + (size_t)(k0 + brow) * N + bn + bcol);
        __syncthreads();
        #pragma unroll
        for (int kk = 0; kk < 8; kk++) {
            float4 a0 = *(const float4*)&As[kk][ty * 8];
            float4 a1 = *(const float4*)&As[kk][ty * 8 + 4];
            float4 b0 = *(const float4*)&Bs[kk][tx * 8];
            float4 b1 = *(const float4*)&Bs[kk][tx * 8 + 4];
            float ra[8] = {a0.x, a0.y, a0.z, a0.w, a1.x, a1.y, a1.z, a1.w};
            float rb[8] = {b0.x, b0.y, b0.z, b0.w, b1.x, b1.y, b1.z, b1.w};
            #pragma unroll
            for (int i = 0; i < 8; i++)
                #pragma unroll
                for (int j = 0; j < 8; j++)
                    acc[i][j] = fmaf(ra[i], rb[j], acc[i][j]);
        }
        __syncthreads();
    }
    #pragma unroll
    for (int i = 0; i < 8; i++) {
        int m = bm + ty * 8 + i;
        #pragma unroll
        for (int j = 0; j < 8; j++) {
            int n = bn + tx * 8 + j;
            float vv = acc[i][j] + bias[n];
            if (MODE == 1) vv = 0.5f * vv * (1.0f + erff(vv * 0.70710678118654752f));
            if (MODE == 2) {
                int b = m >> 9, s = m & 511;
                int h = n >> 6, d = n & 63;
                C[((((size_t)(b * NHsz + h)) * Ssz + s) << 6) + d] = vv;
            } else {
                C[(size_t)m * N + n] = vv;
            }
        }
    }
}

// ---------------- attention: one block per (b, h, q-row) ----------------
__global__ void attn_kernel(const float* __restrict__ q, const float* __restrict__ k,
                            const float* __restrict__ v, const float* __restrict__ amask,
                            float* __restrict__ ctx)
{
    __shared__ float qs[64];
    __shared__ float sc[512];
    __shared__ float red[4];
    __shared__ float part[128];
    int qi = blockIdx.x, h = blockIdx.y, b = blockIdx.z;
    int tid = threadIdx.x;   // 128 threads
    size_t bh = ((size_t)(b * NHsz + h)) * Ssz;
    const float* qrow = q + ((bh + qi) << 6);
    if (tid < 64) qs[tid] = qrow[tid];
    __syncthreads();
    const float* kb = k + (bh << 6);
    const float* vb = v + (bh << 6);
    const float* am = amask + (size_t)b * Ssz;

    float lv[4];
    #pragma unroll
    for (int i = 0; i < 4; i++) {
        int r2 = tid + i * 128;
        const float4* kr = (const float4*)(kb + ((size_t)r2 << 6));
        float acc = 0.0f;
        #pragma unroll
        for (int j = 0; j < 16; j++) {
            float4 kv4 = kr[j];
            float4 qv4 = *(const float4*)(qs + j * 4);
            acc = fmaf(kv4.x, qv4.x, acc);
            acc = fmaf(kv4.y, qv4.y, acc);
            acc = fmaf(kv4.z, qv4.z, acc);
            acc = fmaf(kv4.w, qv4.w, acc);
        }
        lv[i] = acc * 0.125f - 10000.0f * (1.0f - am[r2]);
    }
    float m = fmaxf(fmaxf(lv[0], lv[1]), fmaxf(lv[2], lv[3]));
    m = block_max_128(m, red);
    float ssum = 0.0f;
    #pragma unroll
    for (int i = 0; i < 4; i++) {
        float e = __expf(lv[i] - m);
        sc[tid + i * 128] = e;
        ssum += e;
    }
    ssum = block_sum_128(ssum, red);      // internal syncthreads orders sc writes
    float inv = __frcp_rn(ssum);

    int d = tid & 63, grp = tid >> 6;
    float acc = 0.0f;
    int r0 = grp * 256;
    for (int r2 = r0; r2 < r0 + 256; r2++)
        acc = fmaf(sc[r2], vb[((size_t)r2 << 6) + d], acc);
    part[tid] = acc;
    __syncthreads();
    if (tid < 64) {
        float o = (part[tid] + part[tid + 64]) * inv;
        ctx[((size_t)(b * Ssz + qi)) * Hsz + h * Dsz + tid] = o;
    }
}

// ---------------- pooler: pooled[b] = tanh(x[b,0] @ W + b) ----------------
__global__ void pool_kernel(const float* __restrict__ x, const float* __restrict__ w,
                            const float* __restrict__ pb, float* __restrict__ out)
{
    int n = blockIdx.x * 128 + threadIdx.x;
    int b = blockIdx.y;
    const float* xr = x + (size_t)b * Ssz * Hsz;   // token 0 of batch b
    float acc = 0.0f;
    for (int kk = 0; kk < Hsz; kk++)
        acc = fmaf(xr[kk], w[(size_t)kk * Hsz + n], acc);
    out[(size_t)b * Hsz + n] = tanhf(acc + pb[n]);
}

// ---------------- launch ----------------
extern "C" void kernel_launch(void* const* d_in, const int* in_sizes, int n_in,
                              void* d_out, int out_size)
{
    const int*   ids   = (const int*)d_in[0];
    const int*   tts   = (const int*)d_in[1];
    const float* amask = (const float*)d_in[2];
    const float* imp   = (const float*)d_in[3];
    const float* noise = (const float*)d_in[4];
    const float* we    = (const float*)d_in[5];
    const float* pe    = (const float*)d_in[6];
    const float* te    = (const float*)d_in[7];
    const float* eg    = (const float*)d_in[8];
    const float* ebta  = (const float*)d_in[9];
    const float* Wq    = (const float*)d_in[10];
    const float* bq    = (const float*)d_in[11];
    const float* Wk    = (const float*)d_in[12];
    const float* bk    = (const float*)d_in[13];
    const float* Wv    = (const float*)d_in[14];
    const float* bv    = (const float*)d_in[15];
    const float* Wo    = (const float*)d_in[16];
    const float* bo    = (const float*)d_in[17];
    const float* g1    = (const float*)d_in[18];
    const float* b1    = (const float*)d_in[19];
    const float* Wi    = (const float*)d_in[20];
    const float* bi    = (const float*)d_in[21];
    const float* Wd    = (const float*)d_in[22];
    const float* bd    = (const float*)d_in[23];
    const float* g2    = (const float*)d_in[24];
    const float* b2    = (const float*)d_in[25];
    const float* pw    = (const float*)d_in[26];
    const float* pb    = (const float*)d_in[27];
    float* out = (float*)d_out;

    float *x, *q, *k, *v, *ctx, *tmp, *ffn;
    cudaGetSymbolAddress((void**)&x,   g_x);
    cudaGetSymbolAddress((void**)&q,   g_q);
    cudaGetSymbolAddress((void**)&k,   g_k);
    cudaGetSymbolAddress((void**)&v,   g_v);
    cudaGetSymbolAddress((void**)&ctx, g_ctx);
    cudaGetSymbolAddress((void**)&tmp, g_tmp);
    cudaGetSymbolAddress((void**)&ffn, g_ffn);

    embed_kernel<<<TOK, 256>>>(ids, tts, we, pe, te, eg, ebta, imp, noise, x);

    dim3 gHH(Hsz / 128, TOK / 128);    // (6, 64)
    dim3 gFF(FFsz / 128, TOK / 128);   // (24, 64)

    for (int l = 0; l < Lsz; l++) {
        const float* wq = Wq + (size_t)l * Hsz * Hsz;
        const float* wk = Wk + (size_t)l * Hsz * Hsz;
        const float* wv = Wv + (size_t)l * Hsz * Hsz;
        const float* wo = Wo + (size_t)l * Hsz * Hsz;
        const float* wi = Wi + (size_t)l * Hsz * FFsz;
        const float* wd = Wd + (size_t)l * FFsz * Hsz;
        const float* bql = bq + (size_t)l * Hsz;
        const float* bkl = bk + (size_t)l * Hsz;
        const float* bvl = bv + (size_t)l * Hsz;
        const float* bol = bo + (size_t)l * Hsz;
        const float* bil = bi + (size_t)l * FFsz;
        const float* bdl = bd + (size_t)l * Hsz;
        const float* g1l = g1 + (size_t)l * Hsz;
        const float* b1l = b1 + (size_t)l * Hsz;
        const float* g2l = g2 + (size_t)l * Hsz;
        const float* b2l = b2 + (size_t)l * Hsz;

        gemm128<2><<<gHH, 256>>>(x, wq, bql, q, TOK, Hsz, Hsz);
        gemm128<2><<<gHH, 256>>>(x, wk, bkl, k, TOK, Hsz, Hsz);
        gemm128<2><<<gHH, 256>>>(x, wv, bvl, v, TOK, Hsz, Hsz);
        attn_kernel<<<dim3(Ssz, NHsz, Bsz), 128>>>(q, k, v, amask, ctx);
        gemm128<0><<<gHH, 256>>>(ctx, wo, bol, tmp, TOK, Hsz, Hsz);
        add_ln_kernel<<<TOK, 256>>>(x, tmp, g1l, b1l);
        gemm128<1><<<gFF, 256>>>(x, wi, bil, ffn, TOK, FFsz, Hsz);
        gemm128<0><<<gHH, 256>>>(ffn, wd, bdl, tmp, TOK, Hsz, FFsz);
        add_ln_kernel<<<TOK, 256>>>(x, tmp, g2l, b2l);
    }

    cudaMemcpyAsync(out, x, (size_t)TOK * Hsz * sizeof(float),
                    cudaMemcpyDeviceToDevice);
    pool_kernel<<<dim3(Hsz / 128, Bsz), 128>>>(x, pw, pb, out + (size_t)TOK * Hsz);
}

// round 5
// speedup vs baseline: 5.7802x; 5.7802x over previous
#include <cuda_runtime.h>
#include <cuda_bf16.h>
#include <math.h>

// Problem dims (fixed by reference)
#define Bsz  16
#define Ssz  512
#define Hsz  768
#define Lsz  12
#define NHsz 12
#define FFsz 3072
#define Dsz  64
#define TOK  (Bsz * Ssz)   // 8192 tokens

// ---------------- scratch (static device globals; allocation-free) ----------------
__device__ float g_x  [TOK * Hsz];
__device__ float g_q  [TOK * Hsz];
__device__ float g_k  [TOK * Hsz];
__device__ float g_v  [TOK * Hsz];
__device__ float g_ctx[TOK * Hsz];
__device__ float g_tmp[TOK * Hsz];
__device__ float g_ffn[TOK * FFsz];
__device__ float g_sc [(size_t)Bsz * NHsz * Ssz * Ssz];   // 201 MB scores

// ---------------- block reductions ----------------
__device__ __forceinline__ float block_sum_256(float val, float* red) {
    #pragma unroll
    for (int o = 16; o > 0; o >>= 1) val += __shfl_xor_sync(0xffffffffu, val, o);
    if ((threadIdx.x & 31) == 0) red[threadIdx.x >> 5] = val;
    __syncthreads();
    float s = red[0];
    #pragma unroll
    for (int w = 1; w < 8; w++) s += red[w];
    __syncthreads();
    return s;
}

__device__ __forceinline__ float block_max_128(float val, float* red) {
    #pragma unroll
    for (int o = 16; o > 0; o >>= 1) val = fmaxf(val, __shfl_xor_sync(0xffffffffu, val, o));
    if ((threadIdx.x & 31) == 0) red[threadIdx.x >> 5] = val;
    __syncthreads();
    float m = fmaxf(fmaxf(red[0], red[1]), fmaxf(red[2], red[3]));
    __syncthreads();
    return m;
}

__device__ __forceinline__ float block_sum_128(float val, float* red) {
    #pragma unroll
    for (int o = 16; o > 0; o >>= 1) val += __shfl_xor_sync(0xffffffffu, val, o);
    if ((threadIdx.x & 31) == 0) red[threadIdx.x >> 5] = val;
    __syncthreads();
    float s = red[0] + red[1] + red[2] + red[3];
    __syncthreads();
    return s;
}

// ---------------- embeddings + LN + gaussian noise ----------------
__global__ void embed_kernel(const int* __restrict__ ids, const int* __restrict__ tts,
                             const float* __restrict__ we, const float* __restrict__ pe,
                             const float* __restrict__ te, const float* __restrict__ g,
                             const float* __restrict__ beta, const float* __restrict__ imp,
                             const float* __restrict__ noise, float* __restrict__ x)
{
    __shared__ float red[8];
    int tok = blockIdx.x;
    int s   = tok & (Ssz - 1);
    int tid = threadIdx.x;
    long id = ids[tok];
    long tt = tts[tok];
    float v[3];
    #pragma unroll
    for (int i = 0; i < 3; i++) {
        int hh = tid + i * 256;
        v[i] = we[(size_t)id * Hsz + hh] + pe[(size_t)s * Hsz + hh] + te[(size_t)tt * Hsz + hh];
    }
    float mu = block_sum_256(v[0] + v[1] + v[2], red) * (1.0f / Hsz);
    float d0 = v[0] - mu, d1 = v[1] - mu, d2 = v[2] - mu;
    float var = block_sum_256(d0 * d0 + d1 * d1 + d2 * d2, red) * (1.0f / Hsz);
    float rstd = rsqrtf(var + 1e-12f);
    float ip = imp[tok];
    float sg = 1.0f - ip;
    bool  nz = (ip != 0.0f);
    float dd[3] = {d0, d1, d2};
    #pragma unroll
    for (int i = 0; i < 3; i++) {
        int hh = tid + i * 256;
        float e = dd[i] * rstd * g[hh] + beta[hh];
        if (nz) e = e + noise[(size_t)tok * Hsz + hh] * sg * e;
        x[(size_t)tok * Hsz + hh] = e;
    }
}

// ---------------- residual add + LayerNorm (in-place on x) ----------------
__global__ void add_ln_kernel(float* __restrict__ x, const float* __restrict__ r,
                              const float* __restrict__ g, const float* __restrict__ beta)
{
    __shared__ float red[8];
    int tok = blockIdx.x, tid = threadIdx.x;
    size_t base = (size_t)tok * Hsz;
    float v[3];
    #pragma unroll
    for (int i = 0; i < 3; i++) {
        int hh = tid + i * 256;
        v[i] = x[base + hh] + r[base + hh];
    }
    float mu = block_sum_256(v[0] + v[1] + v[2], red) * (1.0f / Hsz);
    float d0 = v[0] - mu, d1 = v[1] - mu, d2 = v[2] - mu;
    float var = block_sum_256(d0 * d0 + d1 * d1 + d2 * d2, red) * (1.0f / Hsz);
    float rstd = rsqrtf(var + 1e-12f);
    float dd[3] = {d0, d1, d2};
    #pragma unroll
    for (int i = 0; i < 3; i++) {
        int hh = tid + i * 256;
        x[base + hh] = dd[i] * rstd * g[hh] + beta[hh];
    }
}

// ---------------- split-bf16 helpers ----------------
// a = float(hi) + float(lo) to ~16 mantissa bits. Pack pairs for HMMA fragments
// (low 16 bits = first element, high 16 = second).
__device__ __forceinline__ void bsplit(float a, float b, unsigned &h, unsigned &l) {
    __nv_bfloat16 ah = __float2bfloat16(a);
    __nv_bfloat16 bh = __float2bfloat16(b);
    __nv_bfloat16 al = __float2bfloat16(a - __bfloat162float(ah));
    __nv_bfloat16 bl = __float2bfloat16(b - __bfloat162float(bh));
    __nv_bfloat162 th; th.x = ah; th.y = bh;
    __nv_bfloat162 tl; tl.x = al; tl.y = bl;
    h = *reinterpret_cast<unsigned*>(&th);
    l = *reinterpret_cast<unsigned*>(&tl);
}

__device__ __forceinline__ void mma16816(float* d, const unsigned* a, const unsigned* b) {
    asm volatile(
        "mma.sync.aligned.m16n8k16.row.col.f32.bf16.bf16.f32 "
        "{%0,%1,%2,%3}, {%4,%5,%6,%7}, {%8,%9}, {%0,%1,%2,%3};"
        : "+f"(d[0]), "+f"(d[1]), "+f"(d[2]), "+f"(d[3])
        : "r"(a[0]), "r"(a[1]), "r"(a[2]), "r"(a[3]), "r"(b[0]), "r"(b[1]));
}

// ---------------- tensor-core GEMM: C = A[M,K] @ B[K,N] (split-bf16, 3 passes) ----
// Tiles: BM=128, BN=128, BK=32. 256 threads = 8 warps (2x4), warp tile 64x32.
// MODE 0: C += bias (row-major, ldc)
// MODE 1: gelu(C + bias)
// MODE 2: C += bias, scatter to [B,NH,S,D]
// MODE 3: C*0.125 + attn-mask-bias, row-major ldc (scores); amask used, batch z=bh
// MODE 4: plain, write ctx [B,S,H] (N=64 per head), batch z=bh
// TRANSB: B given as [N,K] row-major (used for Q@K^T).
template <int MODE, bool TRANSB>
__global__ void __launch_bounds__(256)
mma_gemm(const float* __restrict__ A, const float* __restrict__ Bm,
         const float* __restrict__ bias, float* __restrict__ C,
         int M, int N, int K, int lda, int ldb, int ldc,
         long long sA, long long sB, long long sC, const float* __restrict__ amask)
{
    __shared__ unsigned Ash[16][132];
    __shared__ unsigned Asl[16][132];
    __shared__ unsigned Bsh[16][132];
    __shared__ unsigned Bsl[16][132];

    int tid = threadIdx.x, lane = tid & 31, warp = tid >> 5;
    int wm = (warp >> 2) * 64;   // 0 or 64
    int wn = (warp & 3) * 32;    // 0,32,64,96
    int bm = blockIdx.y * 128, bn = blockIdx.x * 128;
    int z  = blockIdx.z;
    A  += (size_t)z * sA;
    Bm += (size_t)z * sB;
    C  += (size_t)z * sC;

    float acc[4][4][4];
    #pragma unroll
    for (int i = 0; i < 4; i++)
        #pragma unroll
        for (int j = 0; j < 4; j++)
            #pragma unroll
            for (int t = 0; t < 4; t++) acc[i][j][t] = 0.0f;

    for (int k0 = 0; k0 < K; k0 += 32) {
        // ---- stage A tile (128 x 32) as k-pair-packed hi/lo bf16 ----
        {
            int m = tid >> 1, cb = (tid & 1) * 16;
            const float* Ap = A + (size_t)(bm + m) * lda + k0 + cb;
            #pragma unroll
            for (int cc = 0; cc < 16; cc += 4) {
                float4 v = *(const float4*)(Ap + cc);
                int p = (cb + cc) >> 1;
                unsigned h0, l0, h1, l1;
                bsplit(v.x, v.y, h0, l0);
                bsplit(v.z, v.w, h1, l1);
                Ash[p][m] = h0;     Asl[p][m] = l0;
                Ash[p + 1][m] = h1; Asl[p + 1][m] = l1;
            }
        }
        // ---- stage B tile (32 x 128) ----
        if (TRANSB) {
            int n = tid >> 1, cb = (tid & 1) * 16;
            const float* Bp = Bm + (size_t)(bn + n) * ldb + k0 + cb;
            #pragma unroll
            for (int cc = 0; cc < 16; cc += 4) {
                float4 v = *(const float4*)(Bp + cc);
                int p = (cb + cc) >> 1;
                unsigned h0, l0, h1, l1;
                bsplit(v.x, v.y, h0, l0);
                bsplit(v.z, v.w, h1, l1);
                Bsh[p][n] = h0;     Bsl[p][n] = l0;
                Bsh[p + 1][n] = h1; Bsl[p + 1][n] = l1;
            }
        } else {
            int qd = tid >> 5, n0 = lane * 4;
            bool valid = (bn + n0) < N;
            #pragma unroll
            for (int half = 0; half < 2; half++) {
                int kr = k0 + 2 * qd + half * 16;
                float4 r0, r1;
                if (valid) {
                    r0 = *(const float4*)(Bm + (size_t)kr * ldb + bn + n0);
                    r1 = *(const float4*)(Bm + (size_t)(kr + 1) * ldb + bn + n0);
                } else {
                    r0 = make_float4(0.f, 0.f, 0.f, 0.f);
                    r1 = r0;
                }
                uint4 Hh, Ll;
                bsplit(r0.x, r1.x, Hh.x, Ll.x);
                bsplit(r0.y, r1.y, Hh.y, Ll.y);
                bsplit(r0.z, r1.z, Hh.z, Ll.z);
                bsplit(r0.w, r1.w, Hh.w, Ll.w);
                *(uint4*)&Bsh[qd + half * 8][n0] = Hh;
                *(uint4*)&Bsl[qd + half * 8][n0] = Ll;
            }
        }
        __syncthreads();

        // ---- two k16 steps; 3-pass split MMA each ----
        #pragma unroll
        for (int s = 0; s < 2; s++) {
            int pb = s * 8;
            int t4 = lane & 3, g4 = lane >> 2;
            unsigned ah[4][4], alr[4][4], bb[4][2];
            #pragma unroll
            for (int mt = 0; mt < 4; mt++) {
                int r = wm + mt * 16 + g4;
                ah[mt][0]  = Ash[pb + t4][r];     ah[mt][1]  = Ash[pb + t4][r + 8];
                ah[mt][2]  = Ash[pb + 4 + t4][r]; ah[mt][3]  = Ash[pb + 4 + t4][r + 8];
                alr[mt][0] = Asl[pb + t4][r];     alr[mt][1] = Asl[pb + t4][r + 8];
                alr[mt][2] = Asl[pb + 4 + t4][r]; alr[mt][3] = Asl[pb + 4 + t4][r + 8];
            }
            #pragma unroll
            for (int nt = 0; nt < 4; nt++) {
                int c = wn + nt * 8 + g4;
                bb[nt][0] = Bsh[pb + t4][c];
                bb[nt][1] = Bsh[pb + 4 + t4][c];
            }
            #pragma unroll
            for (int mt = 0; mt < 4; mt++)
                #pragma unroll
                for (int nt = 0; nt < 4; nt++) mma16816(acc[mt][nt], ah[mt], bb[nt]);
            #pragma unroll
            for (int mt = 0; mt < 4; mt++)
                #pragma unroll
                for (int nt = 0; nt < 4; nt++) mma16816(acc[mt][nt], alr[mt], bb[nt]);
            #pragma unroll
            for (int nt = 0; nt < 4; nt++) {
                int c = wn + nt * 8 + g4;
                bb[nt][0] = Bsl[pb + t4][c];
                bb[nt][1] = Bsl[pb + 4 + t4][c];
            }
            #pragma unroll
            for (int mt = 0; mt < 4; mt++)
                #pragma unroll
                for (int nt = 0; nt < 4; nt++) mma16816(acc[mt][nt], ah[mt], bb[nt]);
        }
        __syncthreads();
    }

    // ---- epilogue ----
    int t4 = lane & 3, g4 = lane >> 2;
    #pragma unroll
    for (int mt = 0; mt < 4; mt++) {
        int rg = bm + wm + mt * 16 + g4;
        #pragma unroll
        for (int nt = 0; nt < 4; nt++) {
            int cg = bn + wn + nt * 8 + 2 * t4;
            float* a4 = acc[mt][nt];
            if (MODE == 0 || MODE == 1) {
                float b0v = bias[cg], b1v = bias[cg + 1];
                float v00 = a4[0] + b0v, v01 = a4[1] + b1v;
                float v10 = a4[2] + b0v, v11 = a4[3] + b1v;
                if (MODE == 1) {
                    v00 = 0.5f * v00 * (1.0f + erff(v00 * 0.70710678118654752f));
                    v01 = 0.5f * v01 * (1.0f + erff(v01 * 0.70710678118654752f));
                    v10 = 0.5f * v10 * (1.0f + erff(v10 * 0.70710678118654752f));
                    v11 = 0.5f * v11 * (1.0f + erff(v11 * 0.70710678118654752f));
                }
                *(float2*)&C[(size_t)rg * ldc + cg]       = make_float2(v00, v01);
                *(float2*)&C[(size_t)(rg + 8) * ldc + cg] = make_float2(v10, v11);
            } else if (MODE == 2) {
                float b0v = bias[cg], b1v = bias[cg + 1];
                int h = cg >> 6, d = cg & 63;
                int b_ = rg >> 9, s0 = rg & 511;
                size_t o0 = (((size_t)(b_ * NHsz + h) * Ssz + s0) << 6) + d;
                size_t o1 = (((size_t)(b_ * NHsz + h) * Ssz + s0 + 8) << 6) + d;
                *(float2*)&C[o0] = make_float2(a4[0] + b0v, a4[1] + b1v);
                *(float2*)&C[o1] = make_float2(a4[2] + b0v, a4[3] + b1v);
            } else if (MODE == 3) {
                int b_ = z / NHsz;
                float m0 = (amask[b_ * Ssz + cg]     - 1.0f) * 10000.0f;
                float m1 = (amask[b_ * Ssz + cg + 1] - 1.0f) * 10000.0f;
                *(float2*)&C[(size_t)rg * ldc + cg] =
                    make_float2(a4[0] * 0.125f + m0, a4[1] * 0.125f + m1);
                *(float2*)&C[(size_t)(rg + 8) * ldc + cg] =
                    make_float2(a4[2] * 0.125f + m0, a4[3] * 0.125f + m1);
            } else { // MODE 4
                if (cg < N) {
                    int b_ = z / NHsz, h = z % NHsz;
                    size_t o0 = ((size_t)(b_ * Ssz + rg)) * Hsz + h * Dsz + cg;
                    size_t o1 = ((size_t)(b_ * Ssz + rg + 8)) * Hsz + h * Dsz + cg;
                    *(float2*)&C[o0] = make_float2(a4[0], a4[1]);
                    *(float2*)&C[o1] = make_float2(a4[2], a4[3]);
                }
            }
        }
    }
}

// ---------------- row softmax over scores (mask/scale already applied) ----------
__global__ void softmax_kernel(float* __restrict__ sc)
{
    __shared__ float red[4];
    int row = blockIdx.x, z = blockIdx.y;
    float4* p = (float4*)(sc + ((size_t)z * Ssz + row) * Ssz);
    float4 v = p[threadIdx.x];
    float m = fmaxf(fmaxf(v.x, v.y), fmaxf(v.z, v.w));
    m = block_max_128(m, red);
    v.x = __expf(v.x - m); v.y = __expf(v.y - m);
    v.z = __expf(v.z - m); v.w = __expf(v.w - m);
    float s = block_sum_128(v.x + v.y + v.z + v.w, red);
    float inv = __frcp_rn(s);
    v.x *= inv; v.y *= inv; v.z *= inv; v.w *= inv;
    p[threadIdx.x] = v;
}

// ---------------- pooler: pooled[b] = tanh(x[b,0] @ W + b) ----------------
__global__ void pool_kernel(const float* __restrict__ x, const float* __restrict__ w,
                            const float* __restrict__ pb, float* __restrict__ out)
{
    int n = blockIdx.x * 128 + threadIdx.x;
    int b = blockIdx.y;
    const float* xr = x + (size_t)b * Ssz * Hsz;
    float acc = 0.0f;
    for (int kk = 0; kk < Hsz; kk++)
        acc = fmaf(xr[kk], w[(size_t)kk * Hsz + n], acc);
    out[(size_t)b * Hsz + n] = tanhf(acc + pb[n]);
}

// ---------------- launch ----------------
extern "C" void kernel_launch(void* const* d_in, const int* in_sizes, int n_in,
                              void* d_out, int out_size)
{
    const int*   ids   = (const int*)d_in[0];
    const int*   tts   = (const int*)d_in[1];
    const float* amask = (const float*)d_in[2];
    const float* imp   = (const float*)d_in[3];
    const float* noise = (const float*)d_in[4];
    const float* we    = (const float*)d_in[5];
    const float* pe    = (const float*)d_in[6];
    const float* te    = (const float*)d_in[7];
    const float* eg    = (const float*)d_in[8];
    const float* ebta  = (const float*)d_in[9];
    const float* Wq    = (const float*)d_in[10];
    const float* bq    = (const float*)d_in[11];
    const float* Wk    = (const float*)d_in[12];
    const float* bk    = (const float*)d_in[13];
    const float* Wv    = (const float*)d_in[14];
    const float* bv    = (const float*)d_in[15];
    const float* Wo    = (const float*)d_in[16];
    const float* bo    = (const float*)d_in[17];
    const float* g1    = (const float*)d_in[18];
    const float* b1    = (const float*)d_in[19];
    const float* Wi    = (const float*)d_in[20];
    const float* bi    = (const float*)d_in[21];
    const float* Wd    = (const float*)d_in[22];
    const float* bd    = (const float*)d_in[23];
    const float* g2    = (const float*)d_in[24];
    const float* b2    = (const float*)d_in[25];
    const float* pw    = (const float*)d_in[26];
    const float* pb    = (const float*)d_in[27];
    float* out = (float*)d_out;

    float *x, *q, *k, *v, *ctx, *tmp, *ffn, *sc;
    cudaGetSymbolAddress((void**)&x,   g_x);
    cudaGetSymbolAddress((void**)&q,   g_q);
    cudaGetSymbolAddress((void**)&k,   g_k);
    cudaGetSymbolAddress((void**)&v,   g_v);
    cudaGetSymbolAddress((void**)&ctx, g_ctx);
    cudaGetSymbolAddress((void**)&tmp, g_tmp);
    cudaGetSymbolAddress((void**)&ffn, g_ffn);
    cudaGetSymbolAddress((void**)&sc,  g_sc);

    embed_kernel<<<TOK, 256>>>(ids, tts, we, pe, te, eg, ebta, imp, noise, x);

    dim3 gHH(Hsz / 128, TOK / 128);        // (6, 64)
    dim3 gFF(FFsz / 128, TOK / 128);       // (24, 64)
    dim3 gQK(Ssz / 128, Ssz / 128, Bsz * NHsz);   // (4, 4, 192)
    dim3 gPV(1, Ssz / 128, Bsz * NHsz);           // (1, 4, 192)
    const long long bhQ = (long long)Ssz * Dsz;
    const long long bhS = (long long)Ssz * Ssz;

    for (int l = 0; l < Lsz; l++) {
        const float* wq = Wq + (size_t)l * Hsz * Hsz;
        const float* wk = Wk + (size_t)l * Hsz * Hsz;
        const float* wv = Wv + (size_t)l * Hsz * Hsz;
        const float* wo = Wo + (size_t)l * Hsz * Hsz;
        const float* wi = Wi + (size_t)l * Hsz * FFsz;
        const float* wd = Wd + (size_t)l * FFsz * Hsz;
        const float* bql = bq + (size_t)l * Hsz;
        const float* bkl = bk + (size_t)l * Hsz;
        const float* bvl = bv + (size_t)l * Hsz;
        const float* bol = bo + (size_t)l * Hsz;
        const float* bil = bi + (size_t)l * FFsz;
        const float* bdl = bd + (size_t)l * Hsz;
        const float* g1l = g1 + (size_t)l * Hsz;
        const float* b1l = b1 + (size_t)l * Hsz;
        const float* g2l = g2 + (size_t)l * Hsz;
        const float* b2l = b2 + (size_t)l * Hsz;

        mma_gemm<2, false><<<gHH, 256>>>(x, wq, bql, q, TOK, Hsz, Hsz,
                                         Hsz, Hsz, 0, 0, 0, 0, nullptr);
        mma_gemm<2, false><<<gHH, 256>>>(x, wk, bkl, k, TOK, Hsz, Hsz,
                                         Hsz, Hsz, 0, 0, 0, 0, nullptr);
        mma_gemm<2, false><<<gHH, 256>>>(x, wv, bvl, v, TOK, Hsz, Hsz,
                                         Hsz, Hsz, 0, 0, 0, 0, nullptr);
        // S = Q @ K^T * scale + maskbias   (batched over bh)
        mma_gemm<3, true><<<gQK, 256>>>(q, k, nullptr, sc, Ssz, Ssz, Dsz,
                                        Dsz, Dsz, Ssz, bhQ, bhQ, bhS, amask);
        softmax_kernel<<<dim3(Ssz, Bsz * NHsz), 128>>>(sc);
        // ctx = P @ V  (batched, written straight into [B,S,H])
        mma_gemm<4, false><<<gPV, 256>>>(sc, v, nullptr, ctx, Ssz, Dsz, Ssz,
                                         Ssz, Dsz, 0, bhS, bhQ, 0, nullptr);
        mma_gemm<0, false><<<gHH, 256>>>(ctx, wo, bol, tmp, TOK, Hsz, Hsz,
                                         Hsz, Hsz, Hsz, 0, 0, 0, nullptr);
        add_ln_kernel<<<TOK, 256>>>(x, tmp, g1l, b1l);
        mma_gemm<1, false><<<gFF, 256>>>(x, wi, bil, ffn, TOK, FFsz, Hsz,
                                         Hsz, FFsz, FFsz, 0, 0, 0, nullptr);
        mma_gemm<0, false><<<gHH, 256>>>(ffn, wd, bdl, tmp, TOK, Hsz, FFsz,
                                         FFsz, Hsz, Hsz, 0, 0, 0, nullptr);
        add_ln_kernel<<<TOK, 256>>>(x, tmp, g2l, b2l);
    }

    cudaMemcpyAsync(out, x, (size_t)TOK * Hsz * sizeof(float),
                    cudaMemcpyDeviceToDevice);
    pool_kernel<<<dim3(Hsz / 128, Bsz), 128>>>(x, pw, pb, out + (size_t)TOK * Hsz);
}

// round 9
// speedup vs baseline: 6.6558x; 1.1515x over previous
#include <cuda_runtime.h>
#include <cuda_bf16.h>
#include <math.h>
#include <stdint.h>

// Problem dims (fixed by reference)
#define Bsz  16
#define Ssz  512
#define Hsz  768
#define Lsz  12
#define NHsz 12
#define FFsz 3072
#define Dsz  64
#define TOK  (Bsz * Ssz)   // 8192 tokens

// per-layer prepacked weight element counts (bf16 elements)
#define WHH   (Hsz * Hsz)            // 589824
#define WHF   (Hsz * FFsz)           // 2359296
#define LSTRIDE (4 * WHH + 2 * WHF)  // 7077888

// ---------------- scratch (static device globals; allocation-free) ----------------
__device__ float g_x  [TOK * Hsz];
__device__ float g_q  [TOK * Hsz];
__device__ float g_k  [TOK * Hsz];
__device__ float g_v  [TOK * Hsz];
__device__ float g_ctx[TOK * Hsz];
__device__ float g_tmp[TOK * Hsz];
// scores buffer; FFN intermediate aliases into it (disjoint lifetimes within a layer)
__device__ float g_sc [(size_t)Bsz * NHsz * Ssz * Ssz];     // 201 MB (>= TOK*FFsz*4B)
__device__ __nv_bfloat16 g_whi[(size_t)Lsz * LSTRIDE];      // 170 MB
__device__ __nv_bfloat16 g_wlo[(size_t)Lsz * LSTRIDE];      // 170 MB

// ---------------- split-bf16 helpers ----------------
// a = float(hi) + float(lo) to ~16 mantissa bits. Pack pairs (lo 16 bits = first elem).
__device__ __forceinline__ void bsplit(float a, float b, unsigned &h, unsigned &l) {
    __nv_bfloat16 ah = __float2bfloat16(a);
    __nv_bfloat16 bh = __float2bfloat16(b);
    __nv_bfloat16 al = __float2bfloat16(a - __bfloat162float(ah));
    __nv_bfloat16 bl = __float2bfloat16(b - __bfloat162float(bh));
    __nv_bfloat162 th; th.x = ah; th.y = bh;
    __nv_bfloat162 tl; tl.x = al; tl.y = bl;
    h = *reinterpret_cast<unsigned*>(&th);
    l = *reinterpret_cast<unsigned*>(&tl);
}

__device__ __forceinline__ void mma16816(float* d, const unsigned* a, const unsigned* b) {
    asm volatile(
        "mma.sync.aligned.m16n8k16.row.col.f32.bf16.bf16.f32 "
        "{%0,%1,%2,%3}, {%4,%5,%6,%7}, {%8,%9}, {%0,%1,%2,%3};"
        : "+f"(d[0]), "+f"(d[1]), "+f"(d[2]), "+f"(d[3])
        : "r"(a[0]), "r"(a[1]), "r"(a[2]), "r"(a[3]), "r"(b[0]), "r"(b[1]));
}

// ---------------- block reductions ----------------
__device__ __forceinline__ float block_sum_256(float val, float* red) {
    #pragma unroll
    for (int o = 16; o > 0; o >>= 1) val += __shfl_xor_sync(0xffffffffu, val, o);
    if ((threadIdx.x & 31) == 0) red[threadIdx.x >> 5] = val;
    __syncthreads();
    float s = red[0];
    #pragma unroll
    for (int w = 1; w < 8; w++) s += red[w];
    __syncthreads();
    return s;
}
__device__ __forceinline__ float block_max_128(float val, float* red) {
    #pragma unroll
    for (int o = 16; o > 0; o >>= 1) val = fmaxf(val, __shfl_xor_sync(0xffffffffu, val, o));
    if ((threadIdx.x & 31) == 0) red[threadIdx.x >> 5] = val;
    __syncthreads();
    float m = fmaxf(fmaxf(red[0], red[1]), fmaxf(red[2], red[3]));
    __syncthreads();
    return m;
}
__device__ __forceinline__ float block_sum_128(float val, float* red) {
    #pragma unroll
    for (int o = 16; o > 0; o >>= 1) val += __shfl_xor_sync(0xffffffffu, val, o);
    if ((threadIdx.x & 31) == 0) red[threadIdx.x >> 5] = val;
    __syncthreads();
    float s = red[0] + red[1] + red[2] + red[3];
    __syncthreads();
    return s;
}

// ============ weight prepack: fp32 [K,N] -> fragment-major split-bf16 tiles ========
// Tile = (k32, n128). Per tile per plane: 1024 B-fragments (uint2 each) = 4096 bf16.
// Fragment id f = ((fn*2 + s)*32 + lane), fn = wnq*4+nt (0..15), s = k16 step.
//   col  c  = (fn>>2)*32 + (fn&3)*8 + (lane>>2)
//   pairs   : word0 <-> kpair s*8 + (lane&3), word1 <-> kpair s*8+4+(lane&3)
//   each word packs bf16x2 of W[2p][c], W[2p+1][c].
__global__ void prepack_kernel(const float* __restrict__ W,
                               __nv_bfloat16* __restrict__ hi,
                               __nv_bfloat16* __restrict__ lo, int N)
{
    __shared__ float ws[32][132];
    int kb = blockIdx.x, nb = blockIdx.y;
    int tid = threadIdx.x;
    int k0 = kb * 32, n0 = nb * 128;
    // coalesced load of the 32x128 fp32 tile
    #pragma unroll
    for (int i = 0; i < 4; i++) {
        int idx = tid + i * 256;
        int row = idx >> 5, c4 = (idx & 31) * 4;
        float4 v = *(const float4*)(W + (size_t)(k0 + row) * N + n0 + c4);
        ws[row][c4] = v.x; ws[row][c4 + 1] = v.y;
        ws[row][c4 + 2] = v.z; ws[row][c4 + 3] = v.w;
    }
    __syncthreads();
    // FIX (R8 bug): tile stride is 4096 bf16 elements (1024 uint2 fragments),
    // matching the consumer's 512-uint4 stride. R8 used 2048 -> tiles overlapped.
    size_t tb = ((size_t)nb * gridDim.x + kb) * 4096;   // bf16 elements
    uint2* dh = (uint2*)(hi + tb);
    uint2* dl = (uint2*)(lo + tb);
    #pragma unroll
    for (int i = 0; i < 4; i++) {
        int f = tid + i * 256;
        int lane = f & 31, s = (f >> 5) & 1, fn = f >> 6;
        int c = (fn >> 2) * 32 + (fn & 3) * 8 + (lane >> 2);
        int t4 = lane & 3;
        int p0 = s * 8 + t4, p1 = p0 + 4;
        unsigned h0, l0, h1, l1;
        bsplit(ws[2 * p0][c], ws[2 * p0 + 1][c], h0, l0);
        bsplit(ws[2 * p1][c], ws[2 * p1 + 1][c], h1, l1);
        dh[f] = make_uint2(h0, h1);
        dl[f] = make_uint2(l0, l1);
    }
}

// ======== weight GEMM: C = A[M,K] @ W[K,N] + bias (split-bf16, 3-pass) ============
// 128x128x32 tiles, 8 warps (2x4), fragment-major smem, 2-stage double buffer.
// MODE 0: row-major out. MODE 1: gelu epilogue. MODE 2: scatter to [B,NH,S,D].
// smem per stage (uint4): AH[512] AL[512] BH[512] BL[512]; 2 stages = 64 KB dynamic.
template <int MODE>
__global__ void __launch_bounds__(256)
wgemm(const float* __restrict__ A, const __nv_bfloat16* __restrict__ Bhi,
      const __nv_bfloat16* __restrict__ Blo, const float* __restrict__ bias,
      float* __restrict__ C, int K, int lda, int ldc)
{
    extern __shared__ uint4 sm[];
    int tid = threadIdx.x, lane = tid & 31, warp = tid >> 5;
    int wmq = warp >> 2, wnq = warp & 3;        // warp tile 64x32
    int bn = blockIdx.x * 128, bm = blockIdx.y * 128;
    int nkt = K >> 5;

    float acc[4][4][4];
    #pragma unroll
    for (int i = 0; i < 4; i++)
        #pragma unroll
        for (int j = 0; j < 4; j++)
            #pragma unroll
            for (int t = 0; t < 4; t++) acc[i][j][t] = 0.0f;

    // prefetch registers
    float2 pa[2][4];
    uint4  pbh[2], pbl[2];

    auto LOADA = [&](int kt) {
        int k0 = kt << 5;
        #pragma unroll
        for (int i = 0; i < 2; i++) {
            int fa = tid + i * 256;
            int ln = fa & 31, s = (fa >> 5) & 1, fm = fa >> 6;
            int g4 = ln >> 2, t4 = ln & 3;
            const float* base = A + (size_t)(bm + fm * 16 + g4) * lda + k0 + 2 * (s * 8 + t4);
            pa[i][0] = *(const float2*)(base);
            pa[i][1] = *(const float2*)(base + 8 * (size_t)lda);
            pa[i][2] = *(const float2*)(base + 8);
            pa[i][3] = *(const float2*)(base + 8 * (size_t)lda + 8);
        }
    };
    auto LOADB = [&](int kt) {
        size_t tb = ((size_t)blockIdx.x * nkt + kt) * 512;   // uint4 units
        const uint4* sh = (const uint4*)Bhi + tb;
        const uint4* sl = (const uint4*)Blo + tb;
        pbh[0] = sh[tid]; pbh[1] = sh[tid + 256];
        pbl[0] = sl[tid]; pbl[1] = sl[tid + 256];
    };
    auto STORE = [&](int st) {
        uint4* base = sm + st * 2048;
        #pragma unroll
        for (int i = 0; i < 2; i++) {
            int fa = tid + i * 256;
            unsigned h0, l0, h1, l1, h2, l2, h3, l3;
            bsplit(pa[i][0].x, pa[i][0].y, h0, l0);
            bsplit(pa[i][1].x, pa[i][1].y, h1, l1);
            bsplit(pa[i][2].x, pa[i][2].y, h2, l2);
            bsplit(pa[i][3].x, pa[i][3].y, h3, l3);
            base[fa]       = make_uint4(h0, h1, h2, h3);   // AH
            base[512 + fa] = make_uint4(l0, l1, l2, l3);   // AL
        }
        base[1024 + tid] = pbh[0]; base[1024 + tid + 256] = pbh[1];   // BH
        base[1536 + tid] = pbl[0]; base[1536 + tid + 256] = pbl[1];   // BL
    };

    LOADA(0); LOADB(0); STORE(0);
    __syncthreads();

    for (int kt = 0; kt < nkt; kt++) {
        int st = kt & 1;
        if (kt + 1 < nkt) { LOADA(kt + 1); LOADB(kt + 1); }
        const uint4* AHs = sm + st * 2048;
        const uint4* ALs = AHs + 512;
        const uint2* BHs = (const uint2*)(AHs + 1024);
        const uint2* BLs = (const uint2*)(AHs + 1536);
        #pragma unroll
        for (int s = 0; s < 2; s++) {
            uint4 a_h[4], a_l[4];
            uint2 b_h[4], b_l[4];
            #pragma unroll
            for (int mt = 0; mt < 4; mt++) {
                int idx = ((wmq * 4 + mt) * 2 + s) * 32 + lane;
                a_h[mt] = AHs[idx]; a_l[mt] = ALs[idx];
            }
            #pragma unroll
            for (int nt = 0; nt < 4; nt++) {
                int idx = ((wnq * 4 + nt) * 2 + s) * 32 + lane;
                b_h[nt] = BHs[idx]; b_l[nt] = BLs[idx];
            }
            #pragma unroll
            for (int mt = 0; mt < 4; mt++)
                #pragma unroll
                for (int nt = 0; nt < 4; nt++)
                    mma16816(acc[mt][nt], (const unsigned*)&a_h[mt], (const unsigned*)&b_h[nt]);
            #pragma unroll
            for (int mt = 0; mt < 4; mt++)
                #pragma unroll
                for (int nt = 0; nt < 4; nt++)
                    mma16816(acc[mt][nt], (const unsigned*)&a_l[mt], (const unsigned*)&b_h[nt]);
            #pragma unroll
            for (int mt = 0; mt < 4; mt++)
                #pragma unroll
                for (int nt = 0; nt < 4; nt++)
                    mma16816(acc[mt][nt], (const unsigned*)&a_h[mt], (const unsigned*)&b_l[nt]);
        }
        if (kt + 1 < nkt) STORE((kt + 1) & 1);
        __syncthreads();
    }

    // ---- epilogue (register accum layout identical to R5) ----
    int t4 = lane & 3, g4 = lane >> 2;
    int wm = wmq * 64, wn = wnq * 32;
    #pragma unroll
    for (int mt = 0; mt < 4; mt++) {
        int rg = bm + wm + mt * 16 + g4;
        #pragma unroll
        for (int nt = 0; nt < 4; nt++) {
            int cg = bn + wn + nt * 8 + 2 * t4;
            float* a4 = acc[mt][nt];
            float b0v = bias[cg], b1v = bias[cg + 1];
            float v00 = a4[0] + b0v, v01 = a4[1] + b1v;
            float v10 = a4[2] + b0v, v11 = a4[3] + b1v;
            if (MODE == 1) {
                v00 = 0.5f * v00 * (1.0f + erff(v00 * 0.70710678118654752f));
                v01 = 0.5f * v01 * (1.0f + erff(v01 * 0.70710678118654752f));
                v10 = 0.5f * v10 * (1.0f + erff(v10 * 0.70710678118654752f));
                v11 = 0.5f * v11 * (1.0f + erff(v11 * 0.70710678118654752f));
            }
            if (MODE == 2) {
                int h = cg >> 6, d = cg & 63;
                int b_ = rg >> 9, s0 = rg & 511;
                size_t o0 = (((size_t)(b_ * NHsz + h) * Ssz + s0) << 6) + d;
                size_t o1 = (((size_t)(b_ * NHsz + h) * Ssz + s0 + 8) << 6) + d;
                *(float2*)&C[o0] = make_float2(v00, v01);
                *(float2*)&C[o1] = make_float2(v10, v11);
            } else {
                *(float2*)&C[(size_t)rg * ldc + cg]       = make_float2(v00, v01);
                *(float2*)&C[(size_t)(rg + 8) * ldc + cg] = make_float2(v10, v11);
            }
        }
    }
}

// ---------------- embeddings + LN + gaussian noise ----------------
__global__ void embed_kernel(const int* __restrict__ ids, const int* __restrict__ tts,
                             const float* __restrict__ we, const float* __restrict__ pe,
                             const float* __restrict__ te, const float* __restrict__ g,
                             const float* __restrict__ beta, const float* __restrict__ imp,
                             const float* __restrict__ noise, float* __restrict__ x)
{
    __shared__ float red[8];
    int tok = blockIdx.x;
    int s   = tok & (Ssz - 1);
    int tid = threadIdx.x;
    long id = ids[tok];
    long tt = tts[tok];
    float v[3];
    #pragma unroll
    for (int i = 0; i < 3; i++) {
        int hh = tid + i * 256;
        v[i] = we[(size_t)id * Hsz + hh] + pe[(size_t)s * Hsz + hh] + te[(size_t)tt * Hsz + hh];
    }
    float mu = block_sum_256(v[0] + v[1] + v[2], red) * (1.0f / Hsz);
    float d0 = v[0] - mu, d1 = v[1] - mu, d2 = v[2] - mu;
    float var = block_sum_256(d0 * d0 + d1 * d1 + d2 * d2, red) * (1.0f / Hsz);
    float rstd = rsqrtf(var + 1e-12f);
    float ip = imp[tok];
    float sg = 1.0f - ip;
    bool  nz = (ip != 0.0f);
    float dd[3] = {d0, d1, d2};
    #pragma unroll
    for (int i = 0; i < 3; i++) {
        int hh = tid + i * 256;
        float e = dd[i] * rstd * g[hh] + beta[hh];
        if (nz) e = e + noise[(size_t)tok * Hsz + hh] * sg * e;
        x[(size_t)tok * Hsz + hh] = e;
    }
}

// ---------------- residual add + LayerNorm (in-place on x) ----------------
__global__ void add_ln_kernel(float* __restrict__ x, const float* __restrict__ r,
                              const float* __restrict__ g, const float* __restrict__ beta)
{
    __shared__ float red[8];
    int tok = blockIdx.x, tid = threadIdx.x;
    size_t base = (size_t)tok * Hsz;
    float v[3];
    #pragma unroll
    for (int i = 0; i < 3; i++) {
        int hh = tid + i * 256;
        v[i] = x[base + hh] + r[base + hh];
    }
    float mu = block_sum_256(v[0] + v[1] + v[2], red) * (1.0f / Hsz);
    float d0 = v[0] - mu, d1 = v[1] - mu, d2 = v[2] - mu;
    float var = block_sum_256(d0 * d0 + d1 * d1 + d2 * d2, red) * (1.0f / Hsz);
    float rstd = rsqrtf(var + 1e-12f);
    float dd[3] = {d0, d1, d2};
    #pragma unroll
    for (int i = 0; i < 3; i++) {
        int hh = tid + i * 256;
        x[base + hh] = dd[i] * rstd * g[hh] + beta[hh];
    }
}

// ---------------- mma.sync GEMM (attention only; known-pass from R5) --------------
// MODE 3: scores = A@B^T * 0.125 + maskbias. MODE 4: ctx = P@V to [B,S,H].
template <int MODE, bool TRANSB>
__global__ void __launch_bounds__(256)
mma_gemm(const float* __restrict__ A, const float* __restrict__ Bm,
         float* __restrict__ C, int N, int K, int lda, int ldb, int ldc,
         long long sA, long long sB, long long sC, const float* __restrict__ amask)
{
    __shared__ unsigned Ash[16][132];
    __shared__ unsigned Asl[16][132];
    __shared__ unsigned Bsh[16][132];
    __shared__ unsigned Bsl[16][132];

    int tid = threadIdx.x, lane = tid & 31, warp = tid >> 5;
    int wm = (warp >> 2) * 64;
    int wn = (warp & 3) * 32;
    int bm = blockIdx.y * 128, bn = blockIdx.x * 128;
    int z  = blockIdx.z;
    A  += (size_t)z * sA;
    Bm += (size_t)z * sB;
    C  += (size_t)z * sC;

    float acc[4][4][4];
    #pragma unroll
    for (int i = 0; i < 4; i++)
        #pragma unroll
        for (int j = 0; j < 4; j++)
            #pragma unroll
            for (int t = 0; t < 4; t++) acc[i][j][t] = 0.0f;

    for (int k0 = 0; k0 < K; k0 += 32) {
        {
            int m = tid >> 1, cb = (tid & 1) * 16;
            const float* Ap = A + (size_t)(bm + m) * lda + k0 + cb;
            #pragma unroll
            for (int cc = 0; cc < 16; cc += 4) {
                float4 v = *(const float4*)(Ap + cc);
                int p = (cb + cc) >> 1;
                unsigned h0, l0, h1, l1;
                bsplit(v.x, v.y, h0, l0);
                bsplit(v.z, v.w, h1, l1);
                Ash[p][m] = h0;     Asl[p][m] = l0;
                Ash[p + 1][m] = h1; Asl[p + 1][m] = l1;
            }
        }
        if (TRANSB) {
            int n = tid >> 1, cb = (tid & 1) * 16;
            const float* Bp = Bm + (size_t)(bn + n) * ldb + k0 + cb;
            #pragma unroll
            for (int cc = 0; cc < 16; cc += 4) {
                float4 v = *(const float4*)(Bp + cc);
                int p = (cb + cc) >> 1;
                unsigned h0, l0, h1, l1;
                bsplit(v.x, v.y, h0, l0);
                bsplit(v.z, v.w, h1, l1);
                Bsh[p][n] = h0;     Bsl[p][n] = l0;
                Bsh[p + 1][n] = h1; Bsl[p + 1][n] = l1;
            }
        } else {
            int qd = tid >> 5, n0 = lane * 4;
            bool valid = (bn + n0) < N;
            #pragma unroll
            for (int half = 0; half < 2; half++) {
                int kr = k0 + 2 * qd + half * 16;
                float4 r0, r1;
                if (valid) {
                    r0 = *(const float4*)(Bm + (size_t)kr * ldb + bn + n0);
                    r1 = *(const float4*)(Bm + (size_t)(kr + 1) * ldb + bn + n0);
                } else {
                    r0 = make_float4(0.f, 0.f, 0.f, 0.f);
                    r1 = r0;
                }
                uint4 Hh, Ll;
                bsplit(r0.x, r1.x, Hh.x, Ll.x);
                bsplit(r0.y, r1.y, Hh.y, Ll.y);
                bsplit(r0.z, r1.z, Hh.z, Ll.z);
                bsplit(r0.w, r1.w, Hh.w, Ll.w);
                *(uint4*)&Bsh[qd + half * 8][n0] = Hh;
                *(uint4*)&Bsl[qd + half * 8][n0] = Ll;
            }
        }
        __syncthreads();

        #pragma unroll
        for (int s = 0; s < 2; s++) {
            int pb = s * 8;
            int t4 = lane & 3, g4 = lane >> 2;
            unsigned ah[4][4], alr[4][4], bb[4][2];
            #pragma unroll
            for (int mt = 0; mt < 4; mt++) {
                int r = wm + mt * 16 + g4;
                ah[mt][0]  = Ash[pb + t4][r];     ah[mt][1]  = Ash[pb + t4][r + 8];
                ah[mt][2]  = Ash[pb + 4 + t4][r]; ah[mt][3]  = Ash[pb + 4 + t4][r + 8];
                alr[mt][0] = Asl[pb + t4][r];     alr[mt][1] = Asl[pb + t4][r + 8];
                alr[mt][2] = Asl[pb + 4 + t4][r]; alr[mt][3] = Asl[pb + 4 + t4][r + 8];
            }
            #pragma unroll
            for (int nt = 0; nt < 4; nt++) {
                int c = wn + nt * 8 + g4;
                bb[nt][0] = Bsh[pb + t4][c];
                bb[nt][1] = Bsh[pb + 4 + t4][c];
            }
            #pragma unroll
            for (int mt = 0; mt < 4; mt++)
                #pragma unroll
                for (int nt = 0; nt < 4; nt++) mma16816(acc[mt][nt], ah[mt], bb[nt]);
            #pragma unroll
            for (int mt = 0; mt < 4; mt++)
                #pragma unroll
                for (int nt = 0; nt < 4; nt++) mma16816(acc[mt][nt], alr[mt], bb[nt]);
            #pragma unroll
            for (int nt = 0; nt < 4; nt++) {
                int c = wn + nt * 8 + g4;
                bb[nt][0] = Bsl[pb + t4][c];
                bb[nt][1] = Bsl[pb + 4 + t4][c];
            }
            #pragma unroll
            for (int mt = 0; mt < 4; mt++)
                #pragma unroll
                for (int nt = 0; nt < 4; nt++) mma16816(acc[mt][nt], ah[mt], bb[nt]);
        }
        __syncthreads();
    }

    int t4 = lane & 3, g4 = lane >> 2;
    #pragma unroll
    for (int mt = 0; mt < 4; mt++) {
        int rg = bm + wm + mt * 16 + g4;
        #pragma unroll
        for (int nt = 0; nt < 4; nt++) {
            int cg = bn + wn + nt * 8 + 2 * t4;
            float* a4 = acc[mt][nt];
            if (MODE == 3) {
                int b_ = z / NHsz;
                float m0 = (amask[b_ * Ssz + cg]     - 1.0f) * 10000.0f;
                float m1 = (amask[b_ * Ssz + cg + 1] - 1.0f) * 10000.0f;
                *(float2*)&C[(size_t)rg * ldc + cg] =
                    make_float2(a4[0] * 0.125f + m0, a4[1] * 0.125f + m1);
                *(float2*)&C[(size_t)(rg + 8) * ldc + cg] =
                    make_float2(a4[2] * 0.125f + m0, a4[3] * 0.125f + m1);
            } else { // MODE 4
                if (cg < N) {
                    int b_ = z / NHsz, h = z % NHsz;
                    size_t o0 = ((size_t)(b_ * Ssz + rg)) * Hsz + h * Dsz + cg;
                    size_t o1 = ((size_t)(b_ * Ssz + rg + 8)) * Hsz + h * Dsz + cg;
                    *(float2*)&C[o0] = make_float2(a4[0], a4[1]);
                    *(float2*)&C[o1] = make_float2(a4[2], a4[3]);
                }
            }
        }
    }
}

// ---------------- row softmax over scores (mask/scale already applied) ----------
__global__ void softmax_kernel(float* __restrict__ sc)
{
    __shared__ float red[4];
    int row = blockIdx.x, z = blockIdx.y;
    float4* p = (float4*)(sc + ((size_t)z * Ssz + row) * Ssz);
    float4 v = p[threadIdx.x];
    float m = fmaxf(fmaxf(v.x, v.y), fmaxf(v.z, v.w));
    m = block_max_128(m, red);
    v.x = __expf(v.x - m); v.y = __expf(v.y - m);
    v.z = __expf(v.z - m); v.w = __expf(v.w - m);
    float s = block_sum_128(v.x + v.y + v.z + v.w, red);
    float inv = __frcp_rn(s);
    v.x *= inv; v.y *= inv; v.z *= inv; v.w *= inv;
    p[threadIdx.x] = v;
}

// ---------------- pooler ----------------
__global__ void pool_kernel(const float* __restrict__ x, const float* __restrict__ w,
                            const float* __restrict__ pb, float* __restrict__ out)
{
    int n = blockIdx.x * 128 + threadIdx.x;
    int b = blockIdx.y;
    const float* xr = x + (size_t)b * Ssz * Hsz;
    float acc = 0.0f;
    for (int kk = 0; kk < Hsz; kk++)
        acc = fmaf(xr[kk], w[(size_t)kk * Hsz + n], acc);
    out[(size_t)b * Hsz + n] = tanhf(acc + pb[n]);
}

// ---------------- launch ----------------
#define WG_SMEM (2 * 2048 * 16)   // 64 KB dynamic

extern "C" void kernel_launch(void* const* d_in, const int* in_sizes, int n_in,
                              void* d_out, int out_size)
{
    const int*   ids   = (const int*)d_in[0];
    const int*   tts   = (const int*)d_in[1];
    const float* amask = (const float*)d_in[2];
    const float* imp   = (const float*)d_in[3];
    const float* noise = (const float*)d_in[4];
    const float* we    = (const float*)d_in[5];
    const float* pe    = (const float*)d_in[6];
    const float* te    = (const float*)d_in[7];
    const float* eg    = (const float*)d_in[8];
    const float* ebta  = (const float*)d_in[9];
    const float* Wq    = (const float*)d_in[10];
    const float* bq    = (const float*)d_in[11];
    const float* Wk    = (const float*)d_in[12];
    const float* bk    = (const float*)d_in[13];
    const float* Wv    = (const float*)d_in[14];
    const float* bv    = (const float*)d_in[15];
    const float* Wo    = (const float*)d_in[16];
    const float* bo    = (const float*)d_in[17];
    const float* g1    = (const float*)d_in[18];
    const float* b1    = (const float*)d_in[19];
    const float* Wi    = (const float*)d_in[20];
    const float* bi    = (const float*)d_in[21];
    const float* Wd    = (const float*)d_in[22];
    const float* bd    = (const float*)d_in[23];
    const float* g2    = (const float*)d_in[24];
    const float* b2    = (const float*)d_in[25];
    const float* pw    = (const float*)d_in[26];
    const float* pb    = (const float*)d_in[27];
    float* out = (float*)d_out;

    float *x, *q, *k, *v, *ctx, *tmp, *sc;
    __nv_bfloat16 *whi, *wlo;
    cudaGetSymbolAddress((void**)&x,   g_x);
    cudaGetSymbolAddress((void**)&q,   g_q);
    cudaGetSymbolAddress((void**)&k,   g_k);
    cudaGetSymbolAddress((void**)&v,   g_v);
    cudaGetSymbolAddress((void**)&ctx, g_ctx);
    cudaGetSymbolAddress((void**)&tmp, g_tmp);
    cudaGetSymbolAddress((void**)&sc,  g_sc);
    cudaGetSymbolAddress((void**)&whi, g_whi);
    cudaGetSymbolAddress((void**)&wlo, g_wlo);
    float* ffn = sc;   // aliased: scores and FFN intermediate have disjoint lifetimes

    cudaFuncSetAttribute(wgemm<0>, cudaFuncAttributeMaxDynamicSharedMemorySize, WG_SMEM);
    cudaFuncSetAttribute(wgemm<1>, cudaFuncAttributeMaxDynamicSharedMemorySize, WG_SMEM);
    cudaFuncSetAttribute(wgemm<2>, cudaFuncAttributeMaxDynamicSharedMemorySize, WG_SMEM);

    // ---- prepack all weights into fragment-major split-bf16 tiles ----
    for (int l = 0; l < Lsz; l++) {
        size_t lb = (size_t)l * LSTRIDE;
        prepack_kernel<<<dim3(Hsz / 32, Hsz / 128),  256>>>(Wq + (size_t)l * WHH, whi + lb,           wlo + lb,           Hsz);
        prepack_kernel<<<dim3(Hsz / 32, Hsz / 128),  256>>>(Wk + (size_t)l * WHH, whi + lb + WHH,     wlo + lb + WHH,     Hsz);
        prepack_kernel<<<dim3(Hsz / 32, Hsz / 128),  256>>>(Wv + (size_t)l * WHH, whi + lb + 2 * WHH, wlo + lb + 2 * WHH, Hsz);
        prepack_kernel<<<dim3(Hsz / 32, Hsz / 128),  256>>>(Wo + (size_t)l * WHH, whi + lb + 3 * WHH, wlo + lb + 3 * WHH, Hsz);
        prepack_kernel<<<dim3(Hsz / 32, FFsz / 128), 256>>>(Wi + (size_t)l * WHF, whi + lb + 4 * WHH, wlo + lb + 4 * WHH, FFsz);
        prepack_kernel<<<dim3(FFsz / 32, Hsz / 128), 256>>>(Wd + (size_t)l * WHF, whi + lb + 4 * WHH + WHF, wlo + lb + 4 * WHH + WHF, Hsz);
    }

    embed_kernel<<<TOK, 256>>>(ids, tts, we, pe, te, eg, ebta, imp, noise, x);

    dim3 gHH(Hsz / 128, TOK / 128);               // (6, 64)
    dim3 gFF(FFsz / 128, TOK / 128);              // (24, 64)
    dim3 gQK(Ssz / 128, Ssz / 128, Bsz * NHsz);   // (4, 4, 192)
    dim3 gPV(1, Ssz / 128, Bsz * NHsz);           // (1, 4, 192)
    const long long bhQ = (long long)Ssz * Dsz;
    const long long bhS = (long long)Ssz * Ssz;

    for (int l = 0; l < Lsz; l++) {
        size_t lb = (size_t)l * LSTRIDE;
        const __nv_bfloat16 *qh = whi + lb,           *ql = wlo + lb;
        const __nv_bfloat16 *kh = whi + lb + WHH,     *kl = wlo + lb + WHH;
        const __nv_bfloat16 *vh = whi + lb + 2 * WHH, *vl = wlo + lb + 2 * WHH;
        const __nv_bfloat16 *oh = whi + lb + 3 * WHH, *ol = wlo + lb + 3 * WHH;
        const __nv_bfloat16 *ih = whi + lb + 4 * WHH, *il = wlo + lb + 4 * WHH;
        const __nv_bfloat16 *dh = whi + lb + 4 * WHH + WHF, *dl = wlo + lb + 4 * WHH + WHF;
        const float* bql = bq + (size_t)l * Hsz;
        const float* bkl = bk + (size_t)l * Hsz;
        const float* bvl = bv + (size_t)l * Hsz;
        const float* bol = bo + (size_t)l * Hsz;
        const float* bil = bi + (size_t)l * FFsz;
        const float* bdl = bd + (size_t)l * Hsz;
        const float* g1l = g1 + (size_t)l * Hsz;
        const float* b1l = b1 + (size_t)l * Hsz;
        const float* g2l = g2 + (size_t)l * Hsz;
        const float* b2l = b2 + (size_t)l * Hsz;

        wgemm<2><<<gHH, 256, WG_SMEM>>>(x, qh, ql, bql, q, Hsz, Hsz, 0);
        wgemm<2><<<gHH, 256, WG_SMEM>>>(x, kh, kl, bkl, k, Hsz, Hsz, 0);
        wgemm<2><<<gHH, 256, WG_SMEM>>>(x, vh, vl, bvl, v, Hsz, Hsz, 0);
        mma_gemm<3, true><<<gQK, 256>>>(q, k, sc, Ssz, Dsz, Dsz, Dsz, Ssz,
                                        bhQ, bhQ, bhS, amask);
        softmax_kernel<<<dim3(Ssz, Bsz * NHsz), 128>>>(sc);
        mma_gemm<4, false><<<gPV, 256>>>(sc, v, ctx, Dsz, Ssz, Ssz, Dsz, 0,
                                         bhS, bhQ, 0, nullptr);
        wgemm<0><<<gHH, 256, WG_SMEM>>>(ctx, oh, ol, bol, tmp, Hsz, Hsz, Hsz);
        add_ln_kernel<<<TOK, 256>>>(x, tmp, g1l, b1l);
        wgemm<1><<<gFF, 256, WG_SMEM>>>(x, ih, il, bil, ffn, Hsz, Hsz, FFsz);
        wgemm<0><<<gHH, 256, WG_SMEM>>>(ffn, dh, dl, bdl, tmp, FFsz, FFsz, Hsz);
        add_ln_kernel<<<TOK, 256>>>(x, tmp, g2l, b2l);
    }

    cudaMemcpyAsync(out, x, (size_t)TOK * Hsz * sizeof(float),
                    cudaMemcpyDeviceToDevice);
    pool_kernel<<<dim3(Hsz / 128, Bsz), 128>>>(x, pw, pb, out + (size_t)TOK * Hsz);
}

// round 10
// speedup vs baseline: 7.9005x; 1.1870x over previous
#include <cuda_runtime.h>
#include <cuda_bf16.h>
#include <math.h>
#include <stdint.h>

// Problem dims (fixed by reference)
#define Bsz  16
#define Ssz  512
#define Hsz  768
#define Lsz  12
#define NHsz 12
#define FFsz 3072
#define Dsz  64
#define TOK  (Bsz * Ssz)   // 8192 tokens

// per-layer prepacked weight element counts (bf16 elements)
#define WHH   (Hsz * Hsz)            // 589824
#define WHF   (Hsz * FFsz)           // 2359296
#define LSTRIDE (4 * WHH + 2 * WHF)  // 7077888

// ---------------- scratch (static device globals; allocation-free) ----------------
__device__ float g_x  [TOK * Hsz];
__device__ float g_q  [TOK * Hsz];
__device__ float g_k  [TOK * Hsz];
__device__ float g_v  [TOK * Hsz];
__device__ float g_ctx[TOK * Hsz];
__device__ float g_tmp[TOK * Hsz];
// scores buffer; FFN intermediate aliases into it (disjoint lifetimes within a layer)
__device__ float g_sc [(size_t)Bsz * NHsz * Ssz * Ssz];     // 201 MB (>= TOK*FFsz*4B)
__device__ __nv_bfloat16 g_whi[(size_t)Lsz * LSTRIDE];      // 170 MB
__device__ __nv_bfloat16 g_wlo[(size_t)Lsz * LSTRIDE];      // 170 MB
// converted-activation planes (fragment-major), sized for the largest A (TOK x FFsz)
__device__ __nv_bfloat16 g_axh[(size_t)TOK * FFsz];         // 50 MB
__device__ __nv_bfloat16 g_axl[(size_t)TOK * FFsz];         // 50 MB

// ---------------- split-bf16 helpers ----------------
__device__ __forceinline__ void bsplit(float a, float b, unsigned &h, unsigned &l) {
    __nv_bfloat16 ah = __float2bfloat16(a);
    __nv_bfloat16 bh = __float2bfloat16(b);
    __nv_bfloat16 al = __float2bfloat16(a - __bfloat162float(ah));
    __nv_bfloat16 bl = __float2bfloat16(b - __bfloat162float(bh));
    __nv_bfloat162 th; th.x = ah; th.y = bh;
    __nv_bfloat162 tl; tl.x = al; tl.y = bl;
    h = *reinterpret_cast<unsigned*>(&th);
    l = *reinterpret_cast<unsigned*>(&tl);
}

__device__ __forceinline__ void mma16816(float* d, const unsigned* a, const unsigned* b) {
    asm volatile(
        "mma.sync.aligned.m16n8k16.row.col.f32.bf16.bf16.f32 "
        "{%0,%1,%2,%3}, {%4,%5,%6,%7}, {%8,%9}, {%0,%1,%2,%3};"
        : "+f"(d[0]), "+f"(d[1]), "+f"(d[2]), "+f"(d[3])
        : "r"(a[0]), "r"(a[1]), "r"(a[2]), "r"(a[3]), "r"(b[0]), "r"(b[1]));
}

__device__ __forceinline__ void cp16(uint32_t saddr, const void* g) {
    asm volatile("cp.async.cg.shared.global [%0], [%1], 16;" :: "r"(saddr), "l"(g));
}
#define CP_COMMIT() asm volatile("cp.async.commit_group;")

// ---------------- block reductions ----------------
__device__ __forceinline__ float block_sum_256(float val, float* red) {
    #pragma unroll
    for (int o = 16; o > 0; o >>= 1) val += __shfl_xor_sync(0xffffffffu, val, o);
    if ((threadIdx.x & 31) == 0) red[threadIdx.x >> 5] = val;
    __syncthreads();
    float s = red[0];
    #pragma unroll
    for (int w = 1; w < 8; w++) s += red[w];
    __syncthreads();
    return s;
}
__device__ __forceinline__ float block_max_128(float val, float* red) {
    #pragma unroll
    for (int o = 16; o > 0; o >>= 1) val = fmaxf(val, __shfl_xor_sync(0xffffffffu, val, o));
    if ((threadIdx.x & 31) == 0) red[threadIdx.x >> 5] = val;
    __syncthreads();
    float m = fmaxf(fmaxf(red[0], red[1]), fmaxf(red[2], red[3]));
    __syncthreads();
    return m;
}
__device__ __forceinline__ float block_sum_128(float val, float* red) {
    #pragma unroll
    for (int o = 16; o > 0; o >>= 1) val += __shfl_xor_sync(0xffffffffu, val, o);
    if ((threadIdx.x & 31) == 0) red[threadIdx.x >> 5] = val;
    __syncthreads();
    float s = red[0] + red[1] + red[2] + red[3];
    __syncthreads();
    return s;
}

// ============ weight prepack: fp32 [K,N] -> fragment-major split-bf16 tiles ========
// Tile = (k32, n128): 1024 B-fragments (uint2) = 4096 bf16 per plane.
__global__ void prepack_kernel(const float* __restrict__ W,
                               __nv_bfloat16* __restrict__ hi,
                               __nv_bfloat16* __restrict__ lo, int N)
{
    __shared__ float ws[32][132];
    int kb = blockIdx.x, nb = blockIdx.y;
    int tid = threadIdx.x;
    int k0 = kb * 32, n0 = nb * 128;
    #pragma unroll
    for (int i = 0; i < 4; i++) {
        int idx = tid + i * 256;
        int row = idx >> 5, c4 = (idx & 31) * 4;
        float4 v = *(const float4*)(W + (size_t)(k0 + row) * N + n0 + c4);
        ws[row][c4] = v.x; ws[row][c4 + 1] = v.y;
        ws[row][c4 + 2] = v.z; ws[row][c4 + 3] = v.w;
    }
    __syncthreads();
    size_t tb = ((size_t)nb * gridDim.x + kb) * 4096;   // bf16 elements
    uint2* dh = (uint2*)(hi + tb);
    uint2* dl = (uint2*)(lo + tb);
    #pragma unroll
    for (int i = 0; i < 4; i++) {
        int f = tid + i * 256;
        int lane = f & 31, s = (f >> 5) & 1, fn = f >> 6;
        int c = (fn >> 2) * 32 + (fn & 3) * 8 + (lane >> 2);
        int t4 = lane & 3;
        int p0 = s * 8 + t4, p1 = p0 + 4;
        unsigned h0, l0, h1, l1;
        bsplit(ws[2 * p0][c], ws[2 * p0 + 1][c], h0, l0);
        bsplit(ws[2 * p1][c], ws[2 * p1 + 1][c], h1, l1);
        dh[f] = make_uint2(h0, h1);
        dl[f] = make_uint2(l0, l1);
    }
}

// ============ activation convert: fp32 [M,K] -> fragment-major A tiles =============
// Tile = (m128, k32): 512 A-fragments (uint4) = 4096 bf16 per plane.
// Fragment f = ((fm*2+s)*32+lane): uint4 = words of (r0,p0),(r1,p0),(r0,p1),(r1,p1)
// with r0 = fm*16 + (lane>>2), r1 = r0+8, p0 = s*8+(lane&3), p1 = p0+4.
__global__ void aconv_kernel(const float* __restrict__ A,
                             __nv_bfloat16* __restrict__ hi,
                             __nv_bfloat16* __restrict__ lo, int K)
{
    __shared__ float ws[128][33];
    int kb = blockIdx.x, mb = blockIdx.y;
    int tid = threadIdx.x;
    #pragma unroll
    for (int i = 0; i < 4; i++) {
        int f4 = tid + i * 256;               // 1024 float4s in 128x32 tile
        int row = f4 >> 3, c4 = (f4 & 7) * 4;
        float4 v = *(const float4*)(A + (size_t)(mb * 128 + row) * K + kb * 32 + c4);
        ws[row][c4] = v.x; ws[row][c4 + 1] = v.y;
        ws[row][c4 + 2] = v.z; ws[row][c4 + 3] = v.w;
    }
    __syncthreads();
    size_t tb = ((size_t)mb * gridDim.x + kb) * 512;   // uint4 units
    uint4* dh = (uint4*)hi + tb;
    uint4* dl = (uint4*)lo + tb;
    #pragma unroll
    for (int i = 0; i < 2; i++) {
        int f = tid + i * 256;
        int lane = f & 31, s = (f >> 5) & 1, fm = f >> 6;
        int g4 = lane >> 2, t4 = lane & 3;
        int r0 = fm * 16 + g4, r1 = r0 + 8;
        int p0 = s * 8 + t4, p1 = p0 + 4;
        unsigned h0, l0, h1, l1, h2, l2, h3, l3;
        bsplit(ws[r0][2 * p0], ws[r0][2 * p0 + 1], h0, l0);
        bsplit(ws[r1][2 * p0], ws[r1][2 * p0 + 1], h1, l1);
        bsplit(ws[r0][2 * p1], ws[r0][2 * p1 + 1], h2, l2);
        bsplit(ws[r1][2 * p1], ws[r1][2 * p1 + 1], h3, l3);
        dh[f] = make_uint4(h0, h1, h2, h3);
        dl[f] = make_uint4(l0, l1, l2, l3);
    }
}

// ======== weight GEMM: C = A @ W + bias (split-bf16 3-pass, cp.async pipeline) =====
// A,B both prepacked fragment-major in gmem. 128x128x32 tiles, 8 warps.
// 3-stage smem pipeline, 32KB/stage: AH[512] AL[512] BH[512] BL[512] (uint4).
// MODE 0: row-major out. MODE 1: gelu. MODE 2: scatter to [B,NH,S,D].
template <int MODE>
__global__ void __launch_bounds__(256)
wgemm(const __nv_bfloat16* __restrict__ Ahi, const __nv_bfloat16* __restrict__ Alo,
      const __nv_bfloat16* __restrict__ Bhi, const __nv_bfloat16* __restrict__ Blo,
      const float* __restrict__ bias, float* __restrict__ C, int K, int ldc)
{
    extern __shared__ uint4 sm[];
    int tid = threadIdx.x, lane = tid & 31, warp = tid >> 5;
    int wmq = warp >> 2, wnq = warp & 3;
    int bn = blockIdx.x * 128, bm = blockIdx.y * 128;
    int nkt = K >> 5;
    uint32_t smb = (uint32_t)__cvta_generic_to_shared(sm);

    float acc[4][4][4];
    #pragma unroll
    for (int i = 0; i < 4; i++)
        #pragma unroll
        for (int j = 0; j < 4; j++)
            #pragma unroll
            for (int t = 0; t < 4; t++) acc[i][j][t] = 0.0f;

    auto ISSUE = [&](int kt) {
        int st = kt % 3;
        uint32_t d = smb + st * 32768u;
        size_t ta = ((size_t)blockIdx.y * nkt + kt) * 512;
        size_t tb = ((size_t)blockIdx.x * nkt + kt) * 512;
        const uint4* gah = (const uint4*)Ahi + ta;
        const uint4* gal = (const uint4*)Alo + ta;
        const uint4* gbh = (const uint4*)Bhi + tb;
        const uint4* gbl = (const uint4*)Blo + tb;
        cp16(d + tid * 16u,                   gah + tid);
        cp16(d + (tid + 256) * 16u,           gah + tid + 256);
        cp16(d + 8192u + tid * 16u,           gal + tid);
        cp16(d + 8192u + (tid + 256) * 16u,   gal + tid + 256);
        cp16(d + 16384u + tid * 16u,          gbh + tid);
        cp16(d + 16384u + (tid + 256) * 16u,  gbh + tid + 256);
        cp16(d + 24576u + tid * 16u,          gbl + tid);
        cp16(d + 24576u + (tid + 256) * 16u,  gbl + tid + 256);
        CP_COMMIT();
    };

    ISSUE(0);
    ISSUE(1);

    for (int kt = 0; kt < nkt; kt++) {
        if (kt + 1 < nkt) asm volatile("cp.async.wait_group 1;");
        else              asm volatile("cp.async.wait_group 0;");
        __syncthreads();
        if (kt + 2 < nkt) ISSUE(kt + 2);

        const uint4* AHs = sm + (kt % 3) * 2048;
        const uint4* ALs = AHs + 512;
        const uint2* BHs = (const uint2*)(AHs + 1024);
        const uint2* BLs = (const uint2*)(AHs + 1536);
        #pragma unroll
        for (int s = 0; s < 2; s++) {
            uint4 a_h[4], a_l[4];
            uint2 b_h[4], b_l[4];
            #pragma unroll
            for (int mt = 0; mt < 4; mt++) {
                int idx = ((wmq * 4 + mt) * 2 + s) * 32 + lane;
                a_h[mt] = AHs[idx]; a_l[mt] = ALs[idx];
            }
            #pragma unroll
            for (int nt = 0; nt < 4; nt++) {
                int idx = ((wnq * 4 + nt) * 2 + s) * 32 + lane;
                b_h[nt] = BHs[idx]; b_l[nt] = BLs[idx];
            }
            #pragma unroll
            for (int mt = 0; mt < 4; mt++)
                #pragma unroll
                for (int nt = 0; nt < 4; nt++)
                    mma16816(acc[mt][nt], (const unsigned*)&a_h[mt], (const unsigned*)&b_h[nt]);
            #pragma unroll
            for (int mt = 0; mt < 4; mt++)
                #pragma unroll
                for (int nt = 0; nt < 4; nt++)
                    mma16816(acc[mt][nt], (const unsigned*)&a_l[mt], (const unsigned*)&b_h[nt]);
            #pragma unroll
            for (int mt = 0; mt < 4; mt++)
                #pragma unroll
                for (int nt = 0; nt < 4; nt++)
                    mma16816(acc[mt][nt], (const unsigned*)&a_h[mt], (const unsigned*)&b_l[nt]);
        }
    }

    // ---- epilogue (register accum layout identical to R5/R9) ----
    int t4 = lane & 3, g4 = lane >> 2;
    int wm = wmq * 64, wn = wnq * 32;
    #pragma unroll
    for (int mt = 0; mt < 4; mt++) {
        int rg = bm + wm + mt * 16 + g4;
        #pragma unroll
        for (int nt = 0; nt < 4; nt++) {
            int cg = bn + wn + nt * 8 + 2 * t4;
            float* a4 = acc[mt][nt];
            float b0v = bias[cg], b1v = bias[cg + 1];
            float v00 = a4[0] + b0v, v01 = a4[1] + b1v;
            float v10 = a4[2] + b0v, v11 = a4[3] + b1v;
            if (MODE == 1) {
                v00 = 0.5f * v00 * (1.0f + erff(v00 * 0.70710678118654752f));
                v01 = 0.5f * v01 * (1.0f + erff(v01 * 0.70710678118654752f));
                v10 = 0.5f * v10 * (1.0f + erff(v10 * 0.70710678118654752f));
                v11 = 0.5f * v11 * (1.0f + erff(v11 * 0.70710678118654752f));
            }
            if (MODE == 2) {
                int h = cg >> 6, d = cg & 63;
                int b_ = rg >> 9, s0 = rg & 511;
                size_t o0 = (((size_t)(b_ * NHsz + h) * Ssz + s0) << 6) + d;
                size_t o1 = (((size_t)(b_ * NHsz + h) * Ssz + s0 + 8) << 6) + d;
                *(float2*)&C[o0] = make_float2(v00, v01);
                *(float2*)&C[o1] = make_float2(v10, v11);
            } else {
                *(float2*)&C[(size_t)rg * ldc + cg]       = make_float2(v00, v01);
                *(float2*)&C[(size_t)(rg + 8) * ldc + cg] = make_float2(v10, v11);
            }
        }
    }
}

// ---------------- embeddings + LN + gaussian noise ----------------
__global__ void embed_kernel(const int* __restrict__ ids, const int* __restrict__ tts,
                             const float* __restrict__ we, const float* __restrict__ pe,
                             const float* __restrict__ te, const float* __restrict__ g,
                             const float* __restrict__ beta, const float* __restrict__ imp,
                             const float* __restrict__ noise, float* __restrict__ x)
{
    __shared__ float red[8];
    int tok = blockIdx.x;
    int s   = tok & (Ssz - 1);
    int tid = threadIdx.x;
    long id = ids[tok];
    long tt = tts[tok];
    float v[3];
    #pragma unroll
    for (int i = 0; i < 3; i++) {
        int hh = tid + i * 256;
        v[i] = we[(size_t)id * Hsz + hh] + pe[(size_t)s * Hsz + hh] + te[(size_t)tt * Hsz + hh];
    }
    float mu = block_sum_256(v[0] + v[1] + v[2], red) * (1.0f / Hsz);
    float d0 = v[0] - mu, d1 = v[1] - mu, d2 = v[2] - mu;
    float var = block_sum_256(d0 * d0 + d1 * d1 + d2 * d2, red) * (1.0f / Hsz);
    float rstd = rsqrtf(var + 1e-12f);
    float ip = imp[tok];
    float sg = 1.0f - ip;
    bool  nz = (ip != 0.0f);
    float dd[3] = {d0, d1, d2};
    #pragma unroll
    for (int i = 0; i < 3; i++) {
        int hh = tid + i * 256;
        float e = dd[i] * rstd * g[hh] + beta[hh];
        if (nz) e = e + noise[(size_t)tok * Hsz + hh] * sg * e;
        x[(size_t)tok * Hsz + hh] = e;
    }
}

// ---------------- residual add + LayerNorm (in-place on x) ----------------
__global__ void add_ln_kernel(float* __restrict__ x, const float* __restrict__ r,
                              const float* __restrict__ g, const float* __restrict__ beta)
{
    __shared__ float red[8];
    int tok = blockIdx.x, tid = threadIdx.x;
    size_t base = (size_t)tok * Hsz;
    float v[3];
    #pragma unroll
    for (int i = 0; i < 3; i++) {
        int hh = tid + i * 256;
        v[i] = x[base + hh] + r[base + hh];
    }
    float mu = block_sum_256(v[0] + v[1] + v[2], red) * (1.0f / Hsz);
    float d0 = v[0] - mu, d1 = v[1] - mu, d2 = v[2] - mu;
    float var = block_sum_256(d0 * d0 + d1 * d1 + d2 * d2, red) * (1.0f / Hsz);
    float rstd = rsqrtf(var + 1e-12f);
    float dd[3] = {d0, d1, d2};
    #pragma unroll
    for (int i = 0; i < 3; i++) {
        int hh = tid + i * 256;
        x[base + hh] = dd[i] * rstd * g[hh] + beta[hh];
    }
}

// ---------------- mma.sync GEMM (attention only; known-pass from R5) --------------
// MODE 3: scores = A@B^T * 0.125 + maskbias. MODE 4: ctx = P@V to [B,S,H].
template <int MODE, bool TRANSB>
__global__ void __launch_bounds__(256)
mma_gemm(const float* __restrict__ A, const float* __restrict__ Bm,
         float* __restrict__ C, int N, int K, int lda, int ldb, int ldc,
         long long sA, long long sB, long long sC, const float* __restrict__ amask)
{
    __shared__ unsigned Ash[16][132];
    __shared__ unsigned Asl[16][132];
    __shared__ unsigned Bsh[16][132];
    __shared__ unsigned Bsl[16][132];

    int tid = threadIdx.x, lane = tid & 31, warp = tid >> 5;
    int wm = (warp >> 2) * 64;
    int wn = (warp & 3) * 32;
    int bm = blockIdx.y * 128, bn = blockIdx.x * 128;
    int z  = blockIdx.z;
    A  += (size_t)z * sA;
    Bm += (size_t)z * sB;
    C  += (size_t)z * sC;

    float acc[4][4][4];
    #pragma unroll
    for (int i = 0; i < 4; i++)
        #pragma unroll
        for (int j = 0; j < 4; j++)
            #pragma unroll
            for (int t = 0; t < 4; t++) acc[i][j][t] = 0.0f;

    for (int k0 = 0; k0 < K; k0 += 32) {
        {
            int m = tid >> 1, cb = (tid & 1) * 16;
            const float* Ap = A + (size_t)(bm + m) * lda + k0 + cb;
            #pragma unroll
            for (int cc = 0; cc < 16; cc += 4) {
                float4 v = *(const float4*)(Ap + cc);
                int p = (cb + cc) >> 1;
                unsigned h0, l0, h1, l1;
                bsplit(v.x, v.y, h0, l0);
                bsplit(v.z, v.w, h1, l1);
                Ash[p][m] = h0;     Asl[p][m] = l0;
                Ash[p + 1][m] = h1; Asl[p + 1][m] = l1;
            }
        }
        if (TRANSB) {
            int n = tid >> 1, cb = (tid & 1) * 16;
            const float* Bp = Bm + (size_t)(bn + n) * ldb + k0 + cb;
            #pragma unroll
            for (int cc = 0; cc < 16; cc += 4) {
                float4 v = *(const float4*)(Bp + cc);
                int p = (cb + cc) >> 1;
                unsigned h0, l0, h1, l1;
                bsplit(v.x, v.y, h0, l0);
                bsplit(v.z, v.w, h1, l1);
                Bsh[p][n] = h0;     Bsl[p][n] = l0;
                Bsh[p + 1][n] = h1; Bsl[p + 1][n] = l1;
            }
        } else {
            int qd = tid >> 5, n0 = lane * 4;
            bool valid = (bn + n0) < N;
            #pragma unroll
            for (int half = 0; half < 2; half++) {
                int kr = k0 + 2 * qd + half * 16;
                float4 r0, r1;
                if (valid) {
                    r0 = *(const float4*)(Bm + (size_t)kr * ldb + bn + n0);
                    r1 = *(const float4*)(Bm + (size_t)(kr + 1) * ldb + bn + n0);
                } else {
                    r0 = make_float4(0.f, 0.f, 0.f, 0.f);
                    r1 = r0;
                }
                uint4 Hh, Ll;
                bsplit(r0.x, r1.x, Hh.x, Ll.x);
                bsplit(r0.y, r1.y, Hh.y, Ll.y);
                bsplit(r0.z, r1.z, Hh.z, Ll.z);
                bsplit(r0.w, r1.w, Hh.w, Ll.w);
                *(uint4*)&Bsh[qd + half * 8][n0] = Hh;
                *(uint4*)&Bsl[qd + half * 8][n0] = Ll;
            }
        }
        __syncthreads();

        #pragma unroll
        for (int s = 0; s < 2; s++) {
            int pb = s * 8;
            int t4 = lane & 3, g4 = lane >> 2;
            unsigned ah[4][4], alr[4][4], bb[4][2];
            #pragma unroll
            for (int mt = 0; mt < 4; mt++) {
                int r = wm + mt * 16 + g4;
                ah[mt][0]  = Ash[pb + t4][r];     ah[mt][1]  = Ash[pb + t4][r + 8];
                ah[mt][2]  = Ash[pb + 4 + t4][r]; ah[mt][3]  = Ash[pb + 4 + t4][r + 8];
                alr[mt][0] = Asl[pb + t4][r];     alr[mt][1] = Asl[pb + t4][r + 8];
                alr[mt][2] = Asl[pb + 4 + t4][r]; alr[mt][3] = Asl[pb + 4 + t4][r + 8];
            }
            #pragma unroll
            for (int nt = 0; nt < 4; nt++) {
                int c = wn + nt * 8 + g4;
                bb[nt][0] = Bsh[pb + t4][c];
                bb[nt][1] = Bsh[pb + 4 + t4][c];
            }
            #pragma unroll
            for (int mt = 0; mt < 4; mt++)
                #pragma unroll
                for (int nt = 0; nt < 4; nt++) mma16816(acc[mt][nt], ah[mt], bb[nt]);
            #pragma unroll
            for (int mt = 0; mt < 4; mt++)
                #pragma unroll
                for (int nt = 0; nt < 4; nt++) mma16816(acc[mt][nt], alr[mt], bb[nt]);
            #pragma unroll
            for (int nt = 0; nt < 4; nt++) {
                int c = wn + nt * 8 + g4;
                bb[nt][0] = Bsl[pb + t4][c];
                bb[nt][1] = Bsl[pb + 4 + t4][c];
            }
            #pragma unroll
            for (int mt = 0; mt < 4; mt++)
                #pragma unroll
                for (int nt = 0; nt < 4; nt++) mma16816(acc[mt][nt], ah[mt], bb[nt]);
        }
        __syncthreads();
    }

    int t4 = lane & 3, g4 = lane >> 2;
    #pragma unroll
    for (int mt = 0; mt < 4; mt++) {
        int rg = bm + wm + mt * 16 + g4;
        #pragma unroll
        for (int nt = 0; nt < 4; nt++) {
            int cg = bn + wn + nt * 8 + 2 * t4;
            float* a4 = acc[mt][nt];
            if (MODE == 3) {
                int b_ = z / NHsz;
                float m0 = (amask[b_ * Ssz + cg]     - 1.0f) * 10000.0f;
                float m1 = (amask[b_ * Ssz + cg + 1] - 1.0f) * 10000.0f;
                *(float2*)&C[(size_t)rg * ldc + cg] =
                    make_float2(a4[0] * 0.125f + m0, a4[1] * 0.125f + m1);
                *(float2*)&C[(size_t)(rg + 8) * ldc + cg] =
                    make_float2(a4[2] * 0.125f + m0, a4[3] * 0.125f + m1);
            } else { // MODE 4
                if (cg < N) {
                    int b_ = z / NHsz, h = z % NHsz;
                    size_t o0 = ((size_t)(b_ * Ssz + rg)) * Hsz + h * Dsz + cg;
                    size_t o1 = ((size_t)(b_ * Ssz + rg + 8)) * Hsz + h * Dsz + cg;
                    *(float2*)&C[o0] = make_float2(a4[0], a4[1]);
                    *(float2*)&C[o1] = make_float2(a4[2], a4[3]);
                }
            }
        }
    }
}

// ---------------- row softmax over scores (mask/scale already applied) ----------
__global__ void softmax_kernel(float* __restrict__ sc)
{
    __shared__ float red[4];
    int row = blockIdx.x, z = blockIdx.y;
    float4* p = (float4*)(sc + ((size_t)z * Ssz + row) * Ssz);
    float4 v = p[threadIdx.x];
    float m = fmaxf(fmaxf(v.x, v.y), fmaxf(v.z, v.w));
    m = block_max_128(m, red);
    v.x = __expf(v.x - m); v.y = __expf(v.y - m);
    v.z = __expf(v.z - m); v.w = __expf(v.w - m);
    float s = block_sum_128(v.x + v.y + v.z + v.w, red);
    float inv = __frcp_rn(s);
    v.x *= inv; v.y *= inv; v.z *= inv; v.w *= inv;
    p[threadIdx.x] = v;
}

// ---------------- pooler ----------------
__global__ void pool_kernel(const float* __restrict__ x, const float* __restrict__ w,
                            const float* __restrict__ pb, float* __restrict__ out)
{
    int n = blockIdx.x * 128 + threadIdx.x;
    int b = blockIdx.y;
    const float* xr = x + (size_t)b * Ssz * Hsz;
    float acc = 0.0f;
    for (int kk = 0; kk < Hsz; kk++)
        acc = fmaf(xr[kk], w[(size_t)kk * Hsz + n], acc);
    out[(size_t)b * Hsz + n] = tanhf(acc + pb[n]);
}

// ---------------- launch ----------------
#define WG_SMEM (3 * 2048 * 16)   // 96 KB dynamic, 3 pipeline stages

extern "C" void kernel_launch(void* const* d_in, const int* in_sizes, int n_in,
                              void* d_out, int out_size)
{
    const int*   ids   = (const int*)d_in[0];
    const int*   tts   = (const int*)d_in[1];
    const float* amask = (const float*)d_in[2];
    const float* imp   = (const float*)d_in[3];
    const float* noise = (const float*)d_in[4];
    const float* we    = (const float*)d_in[5];
    const float* pe    = (const float*)d_in[6];
    const float* te    = (const float*)d_in[7];
    const float* eg    = (const float*)d_in[8];
    const float* ebta  = (const float*)d_in[9];
    const float* Wq    = (const float*)d_in[10];
    const float* bq    = (const float*)d_in[11];
    const float* Wk    = (const float*)d_in[12];
    const float* bk    = (const float*)d_in[13];
    const float* Wv    = (const float*)d_in[14];
    const float* bv    = (const float*)d_in[15];
    const float* Wo    = (const float*)d_in[16];
    const float* bo    = (const float*)d_in[17];
    const float* g1    = (const float*)d_in[18];
    const float* b1    = (const float*)d_in[19];
    const float* Wi    = (const float*)d_in[20];
    const float* bi    = (const float*)d_in[21];
    const float* Wd    = (const float*)d_in[22];
    const float* bd    = (const float*)d_in[23];
    const float* g2    = (const float*)d_in[24];
    const float* b2    = (const float*)d_in[25];
    const float* pw    = (const float*)d_in[26];
    const float* pb    = (const float*)d_in[27];
    float* out = (float*)d_out;

    float *x, *q, *k, *v, *ctx, *tmp, *sc;
    __nv_bfloat16 *whi, *wlo, *axh, *axl;
    cudaGetSymbolAddress((void**)&x,   g_x);
    cudaGetSymbolAddress((void**)&q,   g_q);
    cudaGetSymbolAddress((void**)&k,   g_k);
    cudaGetSymbolAddress((void**)&v,   g_v);
    cudaGetSymbolAddress((void**)&ctx, g_ctx);
    cudaGetSymbolAddress((void**)&tmp, g_tmp);
    cudaGetSymbolAddress((void**)&sc,  g_sc);
    cudaGetSymbolAddress((void**)&whi, g_whi);
    cudaGetSymbolAddress((void**)&wlo, g_wlo);
    cudaGetSymbolAddress((void**)&axh, g_axh);
    cudaGetSymbolAddress((void**)&axl, g_axl);
    float* ffn = sc;   // aliased: scores and FFN intermediate have disjoint lifetimes

    cudaFuncSetAttribute(wgemm<0>, cudaFuncAttributeMaxDynamicSharedMemorySize, WG_SMEM);
    cudaFuncSetAttribute(wgemm<1>, cudaFuncAttributeMaxDynamicSharedMemorySize, WG_SMEM);
    cudaFuncSetAttribute(wgemm<2>, cudaFuncAttributeMaxDynamicSharedMemorySize, WG_SMEM);

    // ---- prepack all weights into fragment-major split-bf16 tiles ----
    for (int l = 0; l < Lsz; l++) {
        size_t lb = (size_t)l * LSTRIDE;
        prepack_kernel<<<dim3(Hsz / 32, Hsz / 128),  256>>>(Wq + (size_t)l * WHH, whi + lb,           wlo + lb,           Hsz);
        prepack_kernel<<<dim3(Hsz / 32, Hsz / 128),  256>>>(Wk + (size_t)l * WHH, whi + lb + WHH,     wlo + lb + WHH,     Hsz);
        prepack_kernel<<<dim3(Hsz / 32, Hsz / 128),  256>>>(Wv + (size_t)l * WHH, whi + lb + 2 * WHH, wlo + lb + 2 * WHH, Hsz);
        prepack_kernel<<<dim3(Hsz / 32, Hsz / 128),  256>>>(Wo + (size_t)l * WHH, whi + lb + 3 * WHH, wlo + lb + 3 * WHH, Hsz);
        prepack_kernel<<<dim3(Hsz / 32, FFsz / 128), 256>>>(Wi + (size_t)l * WHF, whi + lb + 4 * WHH, wlo + lb + 4 * WHH, FFsz);
        prepack_kernel<<<dim3(FFsz / 32, Hsz / 128), 256>>>(Wd + (size_t)l * WHF, whi + lb + 4 * WHH + WHF, wlo + lb + 4 * WHH + WHF, Hsz);
    }

    embed_kernel<<<TOK, 256>>>(ids, tts, we, pe, te, eg, ebta, imp, noise, x);

    dim3 gHH(Hsz / 128, TOK / 128);               // (6, 64)
    dim3 gFF(FFsz / 128, TOK / 128);              // (24, 64)
    dim3 gCH(Hsz / 32, TOK / 128);                // aconv grid for K=Hsz
    dim3 gCF(FFsz / 32, TOK / 128);               // aconv grid for K=FFsz
    dim3 gQK(Ssz / 128, Ssz / 128, Bsz * NHsz);   // (4, 4, 192)
    dim3 gPV(1, Ssz / 128, Bsz * NHsz);           // (1, 4, 192)
    const long long bhQ = (long long)Ssz * Dsz;
    const long long bhS = (long long)Ssz * Ssz;

    for (int l = 0; l < Lsz; l++) {
        size_t lb = (size_t)l * LSTRIDE;
        const __nv_bfloat16 *qh = whi + lb,           *ql = wlo + lb;
        const __nv_bfloat16 *kh = whi + lb + WHH,     *kl = wlo + lb + WHH;
        const __nv_bfloat16 *vh = whi + lb + 2 * WHH, *vl = wlo + lb + 2 * WHH;
        const __nv_bfloat16 *oh = whi + lb + 3 * WHH, *ol = wlo + lb + 3 * WHH;
        const __nv_bfloat16 *ih = whi + lb + 4 * WHH, *il = wlo + lb + 4 * WHH;
        const __nv_bfloat16 *dh = whi + lb + 4 * WHH + WHF, *dl = wlo + lb + 4 * WHH + WHF;
        const float* bql = bq + (size_t)l * Hsz;
        const float* bkl = bk + (size_t)l * Hsz;
        const float* bvl = bv + (size_t)l * Hsz;
        const float* bol = bo + (size_t)l * Hsz;
        const float* bil = bi + (size_t)l * FFsz;
        const float* bdl = bd + (size_t)l * Hsz;
        const float* g1l = g1 + (size_t)l * Hsz;
        const float* b1l = b1 + (size_t)l * Hsz;
        const float* g2l = g2 + (size_t)l * Hsz;
        const float* b2l = b2 + (size_t)l * Hsz;

        // QKV share one converted A (x)
        aconv_kernel<<<gCH, 256>>>(x, axh, axl, Hsz);
        wgemm<2><<<gHH, 256, WG_SMEM>>>(axh, axl, qh, ql, bql, q, Hsz, 0);
        wgemm<2><<<gHH, 256, WG_SMEM>>>(axh, axl, kh, kl, bkl, k, Hsz, 0);
        wgemm<2><<<gHH, 256, WG_SMEM>>>(axh, axl, vh, vl, bvl, v, Hsz, 0);
        mma_gemm<3, true><<<gQK, 256>>>(q, k, sc, Ssz, Dsz, Dsz, Dsz, Ssz,
                                        bhQ, bhQ, bhS, amask);
        softmax_kernel<<<dim3(Ssz, Bsz * NHsz), 128>>>(sc);
        mma_gemm<4, false><<<gPV, 256>>>(sc, v, ctx, Dsz, Ssz, Ssz, Dsz, 0,
                                         bhS, bhQ, 0, nullptr);
        aconv_kernel<<<gCH, 256>>>(ctx, axh, axl, Hsz);
        wgemm<0><<<gHH, 256, WG_SMEM>>>(axh, axl, oh, ol, bol, tmp, Hsz, Hsz);
        add_ln_kernel<<<TOK, 256>>>(x, tmp, g1l, b1l);
        aconv_kernel<<<gCH, 256>>>(x, axh, axl, Hsz);
        wgemm<1><<<gFF, 256, WG_SMEM>>>(axh, axl, ih, il, bil, ffn, Hsz, FFsz);
        aconv_kernel<<<gCF, 256>>>(ffn, axh, axl, FFsz);
        wgemm<0><<<gHH, 256, WG_SMEM>>>(axh, axl, dh, dl, bdl, tmp, FFsz, Hsz);
        add_ln_kernel<<<TOK, 256>>>(x, tmp, g2l, b2l);
    }

    cudaMemcpyAsync(out, x, (size_t)TOK * Hsz * sizeof(float),
                    cudaMemcpyDeviceToDevice);
    pool_kernel<<<dim3(Hsz / 128, Bsz), 128>>>(x, pw, pb, out + (size_t)TOK * Hsz);
}

// round 11
// speedup vs baseline: 8.1343x; 1.0296x over previous
#include <cuda_runtime.h>
#include <cuda_bf16.h>
#include <math.h>
#include <stdint.h>

// Problem dims (fixed by reference)
#define Bsz  16
#define Ssz  512
#define Hsz  768
#define Lsz  12
#define NHsz 12
#define FFsz 3072
#define Dsz  64
#define TOK  (Bsz * Ssz)   // 8192 tokens
#define TOKH ((size_t)TOK * Hsz)

// per-layer prepacked weight element counts (bf16 elements)
#define WHH   (Hsz * Hsz)            // 589824
#define WHF   (Hsz * FFsz)           // 2359296
#define LSTRIDE (4 * WHH + 2 * WHF)  // 7077888

// ---------------- scratch (static device globals; allocation-free) ----------------
__device__ float g_x  [TOK * Hsz];
__device__ float g_qkv[3 * TOK * Hsz];                       // fused QKV out [3][B,NH,S,D]
__device__ float g_tmp[TOK * Hsz];
__device__ float g_sc [(size_t)Bsz * NHsz * Ssz * Ssz];      // 201 MB scores
__device__ float g_bqkv[Lsz * 3 * Hsz];                      // concat QKV bias
__device__ __nv_bfloat16 g_whi[(size_t)Lsz * LSTRIDE];       // 170 MB
__device__ __nv_bfloat16 g_wlo[(size_t)Lsz * LSTRIDE];       // 170 MB
// fragment-major activation planes
__device__ __nv_bfloat16 g_xh[TOK * Hsz],  g_xl[TOK * Hsz];   // x planes (QKV / FFN1 A)
__device__ __nv_bfloat16 g_ch[TOK * Hsz],  g_cl[TOK * Hsz];   // ctx planes (AO A)
__device__ __nv_bfloat16 g_fh[(size_t)TOK * FFsz], g_fl[(size_t)TOK * FFsz]; // ffn planes

// ---------------- split-bf16 helpers ----------------
__device__ __forceinline__ void bsplit(float a, float b, unsigned &h, unsigned &l) {
    __nv_bfloat16 ah = __float2bfloat16(a);
    __nv_bfloat16 bh = __float2bfloat16(b);
    __nv_bfloat16 al = __float2bfloat16(a - __bfloat162float(ah));
    __nv_bfloat16 bl = __float2bfloat16(b - __bfloat162float(bh));
    __nv_bfloat162 th; th.x = ah; th.y = bh;
    __nv_bfloat162 tl; tl.x = al; tl.y = bl;
    h = *reinterpret_cast<unsigned*>(&th);
    l = *reinterpret_cast<unsigned*>(&tl);
}

__device__ __forceinline__ void mma16816(float* d, const unsigned* a, const unsigned* b) {
    asm volatile(
        "mma.sync.aligned.m16n8k16.row.col.f32.bf16.bf16.f32 "
        "{%0,%1,%2,%3}, {%4,%5,%6,%7}, {%8,%9}, {%0,%1,%2,%3};"
        : "+f"(d[0]), "+f"(d[1]), "+f"(d[2]), "+f"(d[3])
        : "r"(a[0]), "r"(a[1]), "r"(a[2]), "r"(a[3]), "r"(b[0]), "r"(b[1]));
}

__device__ __forceinline__ void cp16(uint32_t saddr, const void* g) {
    asm volatile("cp.async.cg.shared.global [%0], [%1], 16;" :: "r"(saddr), "l"(g));
}
#define CP_COMMIT() asm volatile("cp.async.commit_group;")

__device__ __forceinline__ float gelu1(float v) {
    return 0.5f * v * (1.0f + erff(v * 0.70710678118654752f));
}

// write one (row r, kpair p) word pair into fragment-major planes (base word arrays)
__device__ __forceinline__ void plane_word(unsigned* ph, unsigned* pl,
                                           int r, int p, int nkt,
                                           unsigned h, unsigned l) {
    int kt = p >> 4, pl_ = p & 15;
    int s = pl_ >> 3, rem = pl_ & 7;
    int t4 = rem & 3, woff = (rem >> 2) * 2;
    int mb = r >> 7, rr = r & 127;
    int fm = rr >> 4, r16 = rr & 15;
    int r1f = r16 >> 3, g4 = r16 & 7;
    int f = (fm * 2 + s) * 32 + g4 * 4 + t4;
    size_t idx = ((size_t)(mb * nkt + kt)) * 2048 + f * 4 + woff + r1f;
    ph[idx] = h; pl[idx] = l;
}

// ---------------- block reductions ----------------
__device__ __forceinline__ float block_sum_256(float val, float* red) {
    #pragma unroll
    for (int o = 16; o > 0; o >>= 1) val += __shfl_xor_sync(0xffffffffu, val, o);
    if ((threadIdx.x & 31) == 0) red[threadIdx.x >> 5] = val;
    __syncthreads();
    float s = red[0];
    #pragma unroll
    for (int w = 1; w < 8; w++) s += red[w];
    __syncthreads();
    return s;
}
__device__ __forceinline__ float block_max_128(float val, float* red) {
    #pragma unroll
    for (int o = 16; o > 0; o >>= 1) val = fmaxf(val, __shfl_xor_sync(0xffffffffu, val, o));
    if ((threadIdx.x & 31) == 0) red[threadIdx.x >> 5] = val;
    __syncthreads();
    float m = fmaxf(fmaxf(red[0], red[1]), fmaxf(red[2], red[3]));
    __syncthreads();
    return m;
}
__device__ __forceinline__ float block_sum_128(float val, float* red) {
    #pragma unroll
    for (int o = 16; o > 0; o >>= 1) val += __shfl_xor_sync(0xffffffffu, val, o);
    if ((threadIdx.x & 31) == 0) red[threadIdx.x >> 5] = val;
    __syncthreads();
    float s = red[0] + red[1] + red[2] + red[3];
    __syncthreads();
    return s;
}

// ============ weight prepack: fp32 [K,N] -> fragment-major split-bf16 tiles ========
__global__ void prepack_kernel(const float* __restrict__ W,
                               __nv_bfloat16* __restrict__ hi,
                               __nv_bfloat16* __restrict__ lo, int N)
{
    __shared__ float ws[32][132];
    int kb = blockIdx.x, nb = blockIdx.y;
    int tid = threadIdx.x;
    int k0 = kb * 32, n0 = nb * 128;
    #pragma unroll
    for (int i = 0; i < 4; i++) {
        int idx = tid + i * 256;
        int row = idx >> 5, c4 = (idx & 31) * 4;
        float4 v = *(const float4*)(W + (size_t)(k0 + row) * N + n0 + c4);
        ws[row][c4] = v.x; ws[row][c4 + 1] = v.y;
        ws[row][c4 + 2] = v.z; ws[row][c4 + 3] = v.w;
    }
    __syncthreads();
    size_t tb = ((size_t)nb * gridDim.x + kb) * 4096;
    uint2* dh = (uint2*)(hi + tb);
    uint2* dl = (uint2*)(lo + tb);
    #pragma unroll
    for (int i = 0; i < 4; i++) {
        int f = tid + i * 256;
        int lane = f & 31, s = (f >> 5) & 1, fn = f >> 6;
        int c = (fn >> 2) * 32 + (fn & 3) * 8 + (lane >> 2);
        int t4 = lane & 3;
        int p0 = s * 8 + t4, p1 = p0 + 4;
        unsigned h0, l0, h1, l1;
        bsplit(ws[2 * p0][c], ws[2 * p0 + 1][c], h0, l0);
        bsplit(ws[2 * p1][c], ws[2 * p1 + 1][c], h1, l1);
        dh[f] = make_uint2(h0, h1);
        dl[f] = make_uint2(l0, l1);
    }
}

// concat per-layer QKV biases into [L, 2304]
__global__ void biascat_kernel(const float* __restrict__ bq, const float* __restrict__ bk,
                               const float* __restrict__ bv, float* __restrict__ o)
{
    int l = blockIdx.x, t = threadIdx.x;
    #pragma unroll
    for (int i = 0; i < 3; i++) {
        int c = t + i * 256;
        o[(size_t)l * 2304 + c]        = bq[(size_t)l * Hsz + c];
        o[(size_t)l * 2304 + 768 + c]  = bk[(size_t)l * Hsz + c];
        o[(size_t)l * 2304 + 1536 + c] = bv[(size_t)l * Hsz + c];
    }
}

// ======== weight GEMM: C = A @ W + bias (split-bf16 3-pass, cp.async pipeline) =====
// A,B prepacked fragment-major in gmem. 128x128x32 tiles, 8 warps, 3-stage pipeline.
// MODE 0: row-major out (ldc). MODE 2: +bias, scatter to fused QKV [3][B,NH,S,D].
// MODE 5: gelu, write A-fragment planes directly (ldc = Ntot/32 tile pitch).
template <int MODE>
__global__ void __launch_bounds__(256)
wgemm(const __nv_bfloat16* __restrict__ Ahi, const __nv_bfloat16* __restrict__ Alo,
      const __nv_bfloat16* __restrict__ Bhi, const __nv_bfloat16* __restrict__ Blo,
      const float* __restrict__ bias, float* __restrict__ C, int K, int ldc,
      __nv_bfloat16* __restrict__ Ph, __nv_bfloat16* __restrict__ Pl)
{
    extern __shared__ uint4 sm[];
    int tid = threadIdx.x, lane = tid & 31, warp = tid >> 5;
    int wmq = warp >> 2, wnq = warp & 3;
    int bn = blockIdx.x * 128, bm = blockIdx.y * 128;
    int nkt = K >> 5;
    uint32_t smb = (uint32_t)__cvta_generic_to_shared(sm);

    float acc[4][4][4];
    #pragma unroll
    for (int i = 0; i < 4; i++)
        #pragma unroll
        for (int j = 0; j < 4; j++)
            #pragma unroll
            for (int t = 0; t < 4; t++) acc[i][j][t] = 0.0f;

    auto ISSUE = [&](int kt) {
        int st = kt % 3;
        uint32_t d = smb + st * 32768u;
        size_t ta = ((size_t)blockIdx.y * nkt + kt) * 512;
        size_t tb = ((size_t)blockIdx.x * nkt + kt) * 512;
        const uint4* gah = (const uint4*)Ahi + ta;
        const uint4* gal = (const uint4*)Alo + ta;
        const uint4* gbh = (const uint4*)Bhi + tb;
        const uint4* gbl = (const uint4*)Blo + tb;
        cp16(d + tid * 16u,                   gah + tid);
        cp16(d + (tid + 256) * 16u,           gah + tid + 256);
        cp16(d + 8192u + tid * 16u,           gal + tid);
        cp16(d + 8192u + (tid + 256) * 16u,   gal + tid + 256);
        cp16(d + 16384u + tid * 16u,          gbh + tid);
        cp16(d + 16384u + (tid + 256) * 16u,  gbh + tid + 256);
        cp16(d + 24576u + tid * 16u,          gbl + tid);
        cp16(d + 24576u + (tid + 256) * 16u,  gbl + tid + 256);
        CP_COMMIT();
    };

    ISSUE(0);
    ISSUE(1);

    for (int kt = 0; kt < nkt; kt++) {
        if (kt + 1 < nkt) asm volatile("cp.async.wait_group 1;");
        else              asm volatile("cp.async.wait_group 0;");
        __syncthreads();
        if (kt + 2 < nkt) ISSUE(kt + 2);

        const uint4* AHs = sm + (kt % 3) * 2048;
        const uint4* ALs = AHs + 512;
        const uint2* BHs = (const uint2*)(AHs + 1024);
        const uint2* BLs = (const uint2*)(AHs + 1536);
        #pragma unroll
        for (int s = 0; s < 2; s++) {
            uint4 a_h[4], a_l[4];
            uint2 b_h[4], b_l[4];
            #pragma unroll
            for (int mt = 0; mt < 4; mt++) {
                int idx = ((wmq * 4 + mt) * 2 + s) * 32 + lane;
                a_h[mt] = AHs[idx]; a_l[mt] = ALs[idx];
            }
            #pragma unroll
            for (int nt = 0; nt < 4; nt++) {
                int idx = ((wnq * 4 + nt) * 2 + s) * 32 + lane;
                b_h[nt] = BHs[idx]; b_l[nt] = BLs[idx];
            }
            #pragma unroll
            for (int mt = 0; mt < 4; mt++)
                #pragma unroll
                for (int nt = 0; nt < 4; nt++)
                    mma16816(acc[mt][nt], (const unsigned*)&a_h[mt], (const unsigned*)&b_h[nt]);
            #pragma unroll
            for (int mt = 0; mt < 4; mt++)
                #pragma unroll
                for (int nt = 0; nt < 4; nt++)
                    mma16816(acc[mt][nt], (const unsigned*)&a_l[mt], (const unsigned*)&b_h[nt]);
            #pragma unroll
            for (int mt = 0; mt < 4; mt++)
                #pragma unroll
                for (int nt = 0; nt < 4; nt++)
                    mma16816(acc[mt][nt], (const unsigned*)&a_h[mt], (const unsigned*)&b_l[nt]);
        }
    }

    // ---- epilogue ----
    int t4 = lane & 3, g4 = lane >> 2;
    int wm = wmq * 64, wn = wnq * 32;
    if (MODE == 5) {
        // write gelu(acc+bias) as A-fragments: tile=(mb, kt=bx*4+wnq), pitch ldc=Ntot/32
        size_t tile = (size_t)blockIdx.y * ldc + blockIdx.x * 4 + wnq;
        uint4* dh = (uint4*)Ph + tile * 512;
        uint4* dl = (uint4*)Pl + tile * 512;
        #pragma unroll
        for (int mt = 0; mt < 4; mt++) {
            int fm = wmq * 4 + mt;
            #pragma unroll
            for (int s = 0; s < 2; s++) {
                float* a0 = acc[mt][2 * s];
                float* a1 = acc[mt][2 * s + 1];
                int cg0 = bn + wn + (2 * s) * 8 + 2 * t4;
                int cg1 = cg0 + 8;
                float v00 = gelu1(a0[0] + bias[cg0]),     v01 = gelu1(a0[1] + bias[cg0 + 1]);
                float v10 = gelu1(a0[2] + bias[cg0]),     v11 = gelu1(a0[3] + bias[cg0 + 1]);
                float u00 = gelu1(a1[0] + bias[cg1]),     u01 = gelu1(a1[1] + bias[cg1 + 1]);
                float u10 = gelu1(a1[2] + bias[cg1]),     u11 = gelu1(a1[3] + bias[cg1 + 1]);
                unsigned h0, l0, h1, l1, h2, l2, h3, l3;
                bsplit(v00, v01, h0, l0);   // (r0, p0)
                bsplit(v10, v11, h1, l1);   // (r1, p0)
                bsplit(u00, u01, h2, l2);   // (r0, p1)
                bsplit(u10, u11, h3, l3);   // (r1, p1)
                int f = (fm * 2 + s) * 32 + lane;
                dh[f] = make_uint4(h0, h1, h2, h3);
                dl[f] = make_uint4(l0, l1, l2, l3);
            }
        }
        return;
    }
    #pragma unroll
    for (int mt = 0; mt < 4; mt++) {
        int rg = bm + wm + mt * 16 + g4;
        #pragma unroll
        for (int nt = 0; nt < 4; nt++) {
            int cg = bn + wn + nt * 8 + 2 * t4;
            float* a4 = acc[mt][nt];
            float b0v = bias[cg], b1v = bias[cg + 1];
            float v00 = a4[0] + b0v, v01 = a4[1] + b1v;
            float v10 = a4[2] + b0v, v11 = a4[3] + b1v;
            if (MODE == 2) {
                int mat = cg / Hsz, c2 = cg - mat * Hsz;
                int h = c2 >> 6, d = c2 & 63;
                int b_ = rg >> 9, s0 = rg & 511;
                size_t base = (size_t)mat * TOKH;
                size_t o0 = base + (((size_t)(b_ * NHsz + h) * Ssz + s0) << 6) + d;
                size_t o1 = base + (((size_t)(b_ * NHsz + h) * Ssz + s0 + 8) << 6) + d;
                *(float2*)&C[o0] = make_float2(v00, v01);
                *(float2*)&C[o1] = make_float2(v10, v11);
            } else {
                *(float2*)&C[(size_t)rg * ldc + cg]       = make_float2(v00, v01);
                *(float2*)&C[(size_t)(rg + 8) * ldc + cg] = make_float2(v10, v11);
            }
        }
    }
}

// ---------------- embeddings + LN + gaussian noise (+ x planes) ----------------
__global__ void embed_kernel(const int* __restrict__ ids, const int* __restrict__ tts,
                             const float* __restrict__ we, const float* __restrict__ pe,
                             const float* __restrict__ te, const float* __restrict__ g,
                             const float* __restrict__ beta, const float* __restrict__ imp,
                             const float* __restrict__ noise, float* __restrict__ x,
                             __nv_bfloat16* __restrict__ xh, __nv_bfloat16* __restrict__ xl)
{
    __shared__ float red[8];
    __shared__ float rowb[Hsz];
    int tok = blockIdx.x;
    int s   = tok & (Ssz - 1);
    int tid = threadIdx.x;
    long id = ids[tok];
    long tt = tts[tok];
    float v[3];
    #pragma unroll
    for (int i = 0; i < 3; i++) {
        int hh = tid + i * 256;
        v[i] = we[(size_t)id * Hsz + hh] + pe[(size_t)s * Hsz + hh] + te[(size_t)tt * Hsz + hh];
    }
    float mu = block_sum_256(v[0] + v[1] + v[2], red) * (1.0f / Hsz);
    float d0 = v[0] - mu, d1 = v[1] - mu, d2 = v[2] - mu;
    float var = block_sum_256(d0 * d0 + d1 * d1 + d2 * d2, red) * (1.0f / Hsz);
    float rstd = rsqrtf(var + 1e-12f);
    float ip = imp[tok];
    float sg = 1.0f - ip;
    bool  nz = (ip != 0.0f);
    float dd[3] = {d0, d1, d2};
    #pragma unroll
    for (int i = 0; i < 3; i++) {
        int hh = tid + i * 256;
        float e = dd[i] * rstd * g[hh] + beta[hh];
        if (nz) e = e + noise[(size_t)tok * Hsz + hh] * sg * e;
        x[(size_t)tok * Hsz + hh] = e;
        rowb[hh] = e;
    }
    __syncthreads();
    #pragma unroll
    for (int i = 0; i < 2; i++) {
        int p = tid + i * 256;
        if (p < Hsz / 2) {
            unsigned h, l;
            bsplit(rowb[2 * p], rowb[2 * p + 1], h, l);
            plane_word((unsigned*)xh, (unsigned*)xl, tok, p, Hsz / 32, h, l);
        }
    }
}

// ---------------- residual add + LayerNorm (in-place on x, + x planes) ------------
__global__ void add_ln_kernel(float* __restrict__ x, const float* __restrict__ r,
                              const float* __restrict__ g, const float* __restrict__ beta,
                              __nv_bfloat16* __restrict__ xh, __nv_bfloat16* __restrict__ xl)
{
    __shared__ float red[8];
    __shared__ float rowb[Hsz];
    int tok = blockIdx.x, tid = threadIdx.x;
    size_t base = (size_t)tok * Hsz;
    float v[3];
    #pragma unroll
    for (int i = 0; i < 3; i++) {
        int hh = tid + i * 256;
        v[i] = x[base + hh] + r[base + hh];
    }
    float mu = block_sum_256(v[0] + v[1] + v[2], red) * (1.0f / Hsz);
    float d0 = v[0] - mu, d1 = v[1] - mu, d2 = v[2] - mu;
    float var = block_sum_256(d0 * d0 + d1 * d1 + d2 * d2, red) * (1.0f / Hsz);
    float rstd = rsqrtf(var + 1e-12f);
    float dd[3] = {d0, d1, d2};
    #pragma unroll
    for (int i = 0; i < 3; i++) {
        int hh = tid + i * 256;
        float e = dd[i] * rstd * g[hh] + beta[hh];
        x[base + hh] = e;
        rowb[hh] = e;
    }
    __syncthreads();
    #pragma unroll
    for (int i = 0; i < 2; i++) {
        int p = tid + i * 256;
        if (p < Hsz / 2) {
            unsigned h, l;
            bsplit(rowb[2 * p], rowb[2 * p + 1], h, l);
            plane_word((unsigned*)xh, (unsigned*)xl, tok, p, Hsz / 32, h, l);
        }
    }
}

// ---------------- mma.sync GEMM (attention) ----------------
// MODE 3: scores = A@B^T * 0.125 + maskbias.
// MODE 4: ctx = P@V written as A-fragment planes (Ph/Pl), no fp32 out.
template <int MODE, bool TRANSB>
__global__ void __launch_bounds__(256)
mma_gemm(const float* __restrict__ A, const float* __restrict__ Bm,
         float* __restrict__ C, int N, int K, int lda, int ldb, int ldc,
         long long sA, long long sB, long long sC, const float* __restrict__ amask,
         __nv_bfloat16* __restrict__ Ph, __nv_bfloat16* __restrict__ Pl)
{
    __shared__ unsigned Ash[16][132];
    __shared__ unsigned Asl[16][132];
    __shared__ unsigned Bsh[16][132];
    __shared__ unsigned Bsl[16][132];

    int tid = threadIdx.x, lane = tid & 31, warp = tid >> 5;
    int wm = (warp >> 2) * 64;
    int wn = (warp & 3) * 32;
    int bm = blockIdx.y * 128, bn = blockIdx.x * 128;
    int z  = blockIdx.z;
    A  += (size_t)z * sA;
    Bm += (size_t)z * sB;
    C  += (size_t)z * sC;

    float acc[4][4][4];
    #pragma unroll
    for (int i = 0; i < 4; i++)
        #pragma unroll
        for (int j = 0; j < 4; j++)
            #pragma unroll
            for (int t = 0; t < 4; t++) acc[i][j][t] = 0.0f;

    for (int k0 = 0; k0 < K; k0 += 32) {
        {
            int m = tid >> 1, cb = (tid & 1) * 16;
            const float* Ap = A + (size_t)(bm + m) * lda + k0 + cb;
            #pragma unroll
            for (int cc = 0; cc < 16; cc += 4) {
                float4 v = *(const float4*)(Ap + cc);
                int p = (cb + cc) >> 1;
                unsigned h0, l0, h1, l1;
                bsplit(v.x, v.y, h0, l0);
                bsplit(v.z, v.w, h1, l1);
                Ash[p][m] = h0;     Asl[p][m] = l0;
                Ash[p + 1][m] = h1; Asl[p + 1][m] = l1;
            }
        }
        if (TRANSB) {
            int n = tid >> 1, cb = (tid & 1) * 16;
            const float* Bp = Bm + (size_t)(bn + n) * ldb + k0 + cb;
            #pragma unroll
            for (int cc = 0; cc < 16; cc += 4) {
                float4 v = *(const float4*)(Bp + cc);
                int p = (cb + cc) >> 1;
                unsigned h0, l0, h1, l1;
                bsplit(v.x, v.y, h0, l0);
                bsplit(v.z, v.w, h1, l1);
                Bsh[p][n] = h0;     Bsl[p][n] = l0;
                Bsh[p + 1][n] = h1; Bsl[p + 1][n] = l1;
            }
        } else {
            int qd = tid >> 5, n0 = lane * 4;
            bool valid = (bn + n0) < N;
            #pragma unroll
            for (int half = 0; half < 2; half++) {
                int kr = k0 + 2 * qd + half * 16;
                float4 r0, r1;
                if (valid) {
                    r0 = *(const float4*)(Bm + (size_t)kr * ldb + bn + n0);
                    r1 = *(const float4*)(Bm + (size_t)(kr + 1) * ldb + bn + n0);
                } else {
                    r0 = make_float4(0.f, 0.f, 0.f, 0.f);
                    r1 = r0;
                }
                uint4 Hh, Ll;
                bsplit(r0.x, r1.x, Hh.x, Ll.x);
                bsplit(r0.y, r1.y, Hh.y, Ll.y);
                bsplit(r0.z, r1.z, Hh.z, Ll.z);
                bsplit(r0.w, r1.w, Hh.w, Ll.w);
                *(uint4*)&Bsh[qd + half * 8][n0] = Hh;
                *(uint4*)&Bsl[qd + half * 8][n0] = Ll;
            }
        }
        __syncthreads();

        #pragma unroll
        for (int s = 0; s < 2; s++) {
            int pb = s * 8;
            int t4 = lane & 3, g4 = lane >> 2;
            unsigned ah[4][4], alr[4][4], bb[4][2];
            #pragma unroll
            for (int mt = 0; mt < 4; mt++) {
                int r = wm + mt * 16 + g4;
                ah[mt][0]  = Ash[pb + t4][r];     ah[mt][1]  = Ash[pb + t4][r + 8];
                ah[mt][2]  = Ash[pb + 4 + t4][r]; ah[mt][3]  = Ash[pb + 4 + t4][r + 8];
                alr[mt][0] = Asl[pb + t4][r];     alr[mt][1] = Asl[pb + t4][r + 8];
                alr[mt][2] = Asl[pb + 4 + t4][r]; alr[mt][3] = Asl[pb + 4 + t4][r + 8];
            }
            #pragma unroll
            for (int nt = 0; nt < 4; nt++) {
                int c = wn + nt * 8 + g4;
                bb[nt][0] = Bsh[pb + t4][c];
                bb[nt][1] = Bsh[pb + 4 + t4][c];
            }
            #pragma unroll
            for (int mt = 0; mt < 4; mt++)
                #pragma unroll
                for (int nt = 0; nt < 4; nt++) mma16816(acc[mt][nt], ah[mt], bb[nt]);
            #pragma unroll
            for (int mt = 0; mt < 4; mt++)
                #pragma unroll
                for (int nt = 0; nt < 4; nt++) mma16816(acc[mt][nt], alr[mt], bb[nt]);
            #pragma unroll
            for (int nt = 0; nt < 4; nt++) {
                int c = wn + nt * 8 + g4;
                bb[nt][0] = Bsl[pb + t4][c];
                bb[nt][1] = Bsl[pb + 4 + t4][c];
            }
            #pragma unroll
            for (int mt = 0; mt < 4; mt++)
                #pragma unroll
                for (int nt = 0; nt < 4; nt++) mma16816(acc[mt][nt], ah[mt], bb[nt]);
        }
        __syncthreads();
    }

    int t4 = lane & 3, g4 = lane >> 2;
    if (MODE == 4) {
        if (wn < 64) {
            int zb = z / NHsz, h = z % NHsz;
            int mb = zb * 4 + blockIdx.y;
            int kt = h * 2 + (warp & 3);
            size_t tile = (size_t)(mb * 24 + kt);
            uint4* dh = (uint4*)Ph + tile * 512;
            uint4* dl = (uint4*)Pl + tile * 512;
            #pragma unroll
            for (int mt = 0; mt < 4; mt++) {
                int fm = (warp >> 2) * 4 + mt;
                #pragma unroll
                for (int s = 0; s < 2; s++) {
                    float* a0 = acc[mt][2 * s];
                    float* a1 = acc[mt][2 * s + 1];
                    unsigned h0, l0, h1, l1, h2, l2, h3, l3;
                    bsplit(a0[0], a0[1], h0, l0);
                    bsplit(a0[2], a0[3], h1, l1);
                    bsplit(a1[0], a1[1], h2, l2);
                    bsplit(a1[2], a1[3], h3, l3);
                    int f = (fm * 2 + s) * 32 + lane;
                    dh[f] = make_uint4(h0, h1, h2, h3);
                    dl[f] = make_uint4(l0, l1, l2, l3);
                }
            }
        }
        return;
    }
    #pragma unroll
    for (int mt = 0; mt < 4; mt++) {
        int rg = bm + wm + mt * 16 + g4;
        #pragma unroll
        for (int nt = 0; nt < 4; nt++) {
            int cg = bn + wn + nt * 8 + 2 * t4;
            float* a4 = acc[mt][nt];
            int b_ = z / NHsz;
            float m0 = (amask[b_ * Ssz + cg]     - 1.0f) * 10000.0f;
            float m1 = (amask[b_ * Ssz + cg + 1] - 1.0f) * 10000.0f;
            *(float2*)&C[(size_t)rg * ldc + cg] =
                make_float2(a4[0] * 0.125f + m0, a4[1] * 0.125f + m1);
            *(float2*)&C[(size_t)(rg + 8) * ldc + cg] =
                make_float2(a4[2] * 0.125f + m0, a4[3] * 0.125f + m1);
        }
    }
}

// ---------------- row softmax over scores (mask/scale already applied) ----------
__global__ void softmax_kernel(float* __restrict__ sc)
{
    __shared__ float red[4];
    int row = blockIdx.x, z = blockIdx.y;
    float4* p = (float4*)(sc + ((size_t)z * Ssz + row) * Ssz);
    float4 v = p[threadIdx.x];
    float m = fmaxf(fmaxf(v.x, v.y), fmaxf(v.z, v.w));
    m = block_max_128(m, red);
    v.x = __expf(v.x - m); v.y = __expf(v.y - m);
    v.z = __expf(v.z - m); v.w = __expf(v.w - m);
    float s = block_sum_128(v.x + v.y + v.z + v.w, red);
    float inv = __frcp_rn(s);
    v.x *= inv; v.y *= inv; v.z *= inv; v.w *= inv;
    p[threadIdx.x] = v;
}

// ---------------- pooler ----------------
__global__ void pool_kernel(const float* __restrict__ x, const float* __restrict__ w,
                            const float* __restrict__ pb, float* __restrict__ out)
{
    int n = blockIdx.x * 128 + threadIdx.x;
    int b = blockIdx.y;
    const float* xr = x + (size_t)b * Ssz * Hsz;
    float acc = 0.0f;
    for (int kk = 0; kk < Hsz; kk++)
        acc = fmaf(xr[kk], w[(size_t)kk * Hsz + n], acc);
    out[(size_t)b * Hsz + n] = tanhf(acc + pb[n]);
}

// ---------------- launch ----------------
#define WG_SMEM (3 * 2048 * 16)   // 96 KB dynamic, 3 pipeline stages

extern "C" void kernel_launch(void* const* d_in, const int* in_sizes, int n_in,
                              void* d_out, int out_size)
{
    const int*   ids   = (const int*)d_in[0];
    const int*   tts   = (const int*)d_in[1];
    const float* amask = (const float*)d_in[2];
    const float* imp   = (const float*)d_in[3];
    const float* noise = (const float*)d_in[4];
    const float* we    = (const float*)d_in[5];
    const float* pe    = (const float*)d_in[6];
    const float* te    = (const float*)d_in[7];
    const float* eg    = (const float*)d_in[8];
    const float* ebta  = (const float*)d_in[9];
    const float* Wq    = (const float*)d_in[10];
    const float* bq    = (const float*)d_in[11];
    const float* Wk    = (const float*)d_in[12];
    const float* bk    = (const float*)d_in[13];
    const float* Wv    = (const float*)d_in[14];
    const float* bv    = (const float*)d_in[15];
    const float* Wo    = (const float*)d_in[16];
    const float* bo    = (const float*)d_in[17];
    const float* g1    = (const float*)d_in[18];
    const float* b1    = (const float*)d_in[19];
    const float* Wi    = (const float*)d_in[20];
    const float* bi    = (const float*)d_in[21];
    const float* Wd    = (const float*)d_in[22];
    const float* bd    = (const float*)d_in[23];
    const float* g2    = (const float*)d_in[24];
    const float* b2    = (const float*)d_in[25];
    const float* pw    = (const float*)d_in[26];
    const float* pb    = (const float*)d_in[27];
    float* out = (float*)d_out;

    float *x, *qkv, *tmp, *sc, *bqkv;
    __nv_bfloat16 *whi, *wlo, *xh, *xl, *ch, *cl, *fh, *fl;
    cudaGetSymbolAddress((void**)&x,    g_x);
    cudaGetSymbolAddress((void**)&qkv,  g_qkv);
    cudaGetSymbolAddress((void**)&tmp,  g_tmp);
    cudaGetSymbolAddress((void**)&sc,   g_sc);
    cudaGetSymbolAddress((void**)&bqkv, g_bqkv);
    cudaGetSymbolAddress((void**)&whi,  g_whi);
    cudaGetSymbolAddress((void**)&wlo,  g_wlo);
    cudaGetSymbolAddress((void**)&xh,   g_xh);
    cudaGetSymbolAddress((void**)&xl,   g_xl);
    cudaGetSymbolAddress((void**)&ch,   g_ch);
    cudaGetSymbolAddress((void**)&cl,   g_cl);
    cudaGetSymbolAddress((void**)&fh,   g_fh);
    cudaGetSymbolAddress((void**)&fl,   g_fl);

    cudaFuncSetAttribute(wgemm<0>, cudaFuncAttributeMaxDynamicSharedMemorySize, WG_SMEM);
    cudaFuncSetAttribute(wgemm<2>, cudaFuncAttributeMaxDynamicSharedMemorySize, WG_SMEM);
    cudaFuncSetAttribute(wgemm<5>, cudaFuncAttributeMaxDynamicSharedMemorySize, WG_SMEM);

    // ---- prepack weights + concat QKV biases ----
    for (int l = 0; l < Lsz; l++) {
        size_t lb = (size_t)l * LSTRIDE;
        prepack_kernel<<<dim3(Hsz / 32, Hsz / 128),  256>>>(Wq + (size_t)l * WHH, whi + lb,           wlo + lb,           Hsz);
        prepack_kernel<<<dim3(Hsz / 32, Hsz / 128),  256>>>(Wk + (size_t)l * WHH, whi + lb + WHH,     wlo + lb + WHH,     Hsz);
        prepack_kernel<<<dim3(Hsz / 32, Hsz / 128),  256>>>(Wv + (size_t)l * WHH, whi + lb + 2 * WHH, wlo + lb + 2 * WHH, Hsz);
        prepack_kernel<<<dim3(Hsz / 32, Hsz / 128),  256>>>(Wo + (size_t)l * WHH, whi + lb + 3 * WHH, wlo + lb + 3 * WHH, Hsz);
        prepack_kernel<<<dim3(Hsz / 32, FFsz / 128), 256>>>(Wi + (size_t)l * WHF, whi + lb + 4 * WHH, wlo + lb + 4 * WHH, FFsz);
        prepack_kernel<<<dim3(FFsz / 32, Hsz / 128), 256>>>(Wd + (size_t)l * WHF, whi + lb + 4 * WHH + WHF, wlo + lb + 4 * WHH + WHF, Hsz);
    }
    biascat_kernel<<<Lsz, 256>>>(bq, bk, bv, bqkv);

    embed_kernel<<<TOK, 256>>>(ids, tts, we, pe, te, eg, ebta, imp, noise, x, xh, xl);

    dim3 gQKV(3 * Hsz / 128, TOK / 128);          // (18, 64) fused QKV
    dim3 gHH(Hsz / 128, TOK / 128);               // (6, 64)
    dim3 gFF(FFsz / 128, TOK / 128);              // (24, 64)
    dim3 gQK(Ssz / 128, Ssz / 128, Bsz * NHsz);   // (4, 4, 192)
    dim3 gPV(1, Ssz / 128, Bsz * NHsz);           // (1, 4, 192)
    const long long bhQ = (long long)Ssz * Dsz;
    const long long bhS = (long long)Ssz * Ssz;
    float* qb = qkv;
    float* kb_ = qkv + TOKH;
    float* vb = qkv + 2 * TOKH;

    for (int l = 0; l < Lsz; l++) {
        size_t lb = (size_t)l * LSTRIDE;
        const __nv_bfloat16 *qwh = whi + lb,               *qwl = wlo + lb;      // QKV combined
        const __nv_bfloat16 *oh  = whi + lb + 3 * WHH,     *ol  = wlo + lb + 3 * WHH;
        const __nv_bfloat16 *ih  = whi + lb + 4 * WHH,     *il  = wlo + lb + 4 * WHH;
        const __nv_bfloat16 *dh  = whi + lb + 4 * WHH + WHF, *dl = wlo + lb + 4 * WHH + WHF;
        const float* bqkvl = bqkv + (size_t)l * 2304;
        const float* bol = bo + (size_t)l * Hsz;
        const float* bil = bi + (size_t)l * FFsz;
        const float* bdl = bd + (size_t)l * Hsz;
        const float* g1l = g1 + (size_t)l * Hsz;
        const float* b1l = b1 + (size_t)l * Hsz;
        const float* g2l = g2 + (size_t)l * Hsz;
        const float* b2l = b2 + (size_t)l * Hsz;

        // fused QKV (N=2304) from x planes
        wgemm<2><<<gQKV, 256, WG_SMEM>>>(xh, xl, qwh, qwl, bqkvl, qkv, Hsz, 0, nullptr, nullptr);
        mma_gemm<3, true><<<gQK, 256>>>(qb, kb_, sc, Ssz, Dsz, Dsz, Dsz, Ssz,
                                        bhQ, bhQ, bhS, amask, nullptr, nullptr);
        softmax_kernel<<<dim3(Ssz, Bsz * NHsz), 128>>>(sc);
        // PV -> ctx planes directly
        mma_gemm<4, false><<<gPV, 256>>>(sc, vb, nullptr, Dsz, Ssz, Ssz, Dsz, 0,
                                         bhS, bhQ, 0, nullptr, ch, cl);
        wgemm<0><<<gHH, 256, WG_SMEM>>>(ch, cl, oh, ol, bol, tmp, Hsz, Hsz, nullptr, nullptr);
        add_ln_kernel<<<TOK, 256>>>(x, tmp, g1l, b1l, xh, xl);
        // FFN1 -> ffn planes directly (gelu fused)
        wgemm<5><<<gFF, 256, WG_SMEM>>>(xh, xl, ih, il, bil, nullptr, Hsz, FFsz / 32, fh, fl);
        wgemm<0><<<gHH, 256, WG_SMEM>>>(fh, fl, dh, dl, bdl, tmp, FFsz, Hsz, nullptr, nullptr);
        add_ln_kernel<<<TOK, 256>>>(x, tmp, g2l, b2l, xh, xl);
    }

    cudaMemcpyAsync(out, x, (size_t)TOK * Hsz * sizeof(float),
                    cudaMemcpyDeviceToDevice);
    pool_kernel<<<dim3(Hsz / 128, Bsz), 128>>>(x, pw, pb, out + (size_t)TOK * Hsz);
}

// round 16
// speedup vs baseline: 8.7882x; 1.0804x over previous
#include <cuda_runtime.h>
#include <cuda_bf16.h>
#include <math.h>
#include <stdint.h>

// Problem dims (fixed by reference)
#define Bsz  16
#define Ssz  512
#define Hsz  768
#define Lsz  12
#define NHsz 12
#define FFsz 3072
#define Dsz  64
#define TOK  (Bsz * Ssz)   // 8192 tokens
#define TOKH ((size_t)TOK * Hsz)

// per-layer prepacked weight element counts (bf16 elements)
#define WHH   (Hsz * Hsz)            // 589824
#define WHF   (Hsz * FFsz)           // 2359296
#define LSTRIDE (4 * WHH + 2 * WHF)  // 7077888

// ---------------- scratch (static device globals; allocation-free) ----------------
__device__ float g_x  [TOK * Hsz];
__device__ float g_qkv[3 * TOK * Hsz];                       // fused QKV out [3][B,NH,S,D]
__device__ float g_tmp[TOK * Hsz];
__device__ float g_sc [(size_t)Bsz * NHsz * Ssz * Ssz];      // 201 MB scores
__device__ float g_bqkv[Lsz * 3 * Hsz];                      // concat QKV bias
__device__ __nv_bfloat16 g_whi[(size_t)Lsz * LSTRIDE];       // 170 MB
__device__ __nv_bfloat16 g_wlo[(size_t)Lsz * LSTRIDE];       // 170 MB
// fragment-major activation planes
__device__ __nv_bfloat16 g_xh[TOK * Hsz],  g_xl[TOK * Hsz];   // x planes (QKV / FFN1 A)
__device__ __nv_bfloat16 g_ch[TOK * Hsz],  g_cl[TOK * Hsz];   // ctx planes (AO A)
__device__ __nv_bfloat16 g_fh[(size_t)TOK * FFsz], g_fl[(size_t)TOK * FFsz]; // ffn planes

// ---------------- split-bf16 helpers ----------------
__device__ __forceinline__ void bsplit(float a, float b, unsigned &h, unsigned &l) {
    __nv_bfloat16 ah = __float2bfloat16(a);
    __nv_bfloat16 bh = __float2bfloat16(b);
    __nv_bfloat16 al = __float2bfloat16(a - __bfloat162float(ah));
    __nv_bfloat16 bl = __float2bfloat16(b - __bfloat162float(bh));
    __nv_bfloat162 th; th.x = ah; th.y = bh;
    __nv_bfloat162 tl; tl.x = al; tl.y = bl;
    h = *reinterpret_cast<unsigned*>(&th);
    l = *reinterpret_cast<unsigned*>(&tl);
}

__device__ __forceinline__ void mma16816(float* d, const unsigned* a, const unsigned* b) {
    asm volatile(
        "mma.sync.aligned.m16n8k16.row.col.f32.bf16.bf16.f32 "
        "{%0,%1,%2,%3}, {%4,%5,%6,%7}, {%8,%9}, {%0,%1,%2,%3};"
        : "+f"(d[0]), "+f"(d[1]), "+f"(d[2]), "+f"(d[3])
        : "r"(a[0]), "r"(a[1]), "r"(a[2]), "r"(a[3]), "r"(b[0]), "r"(b[1]));
}

__device__ __forceinline__ void cp16(uint32_t saddr, const void* g) {
    asm volatile("cp.async.cg.shared.global [%0], [%1], 16;" :: "r"(saddr), "l"(g));
}
#define CP_COMMIT() asm volatile("cp.async.commit_group;")

__device__ __forceinline__ float gelu1(float v) {
    return 0.5f * v * (1.0f + erff(v * 0.70710678118654752f));
}

// write one (row r, kpair p) word pair into fragment-major planes (base word arrays)
__device__ __forceinline__ void plane_word(unsigned* ph, unsigned* pl,
                                           int r, int p, int nkt,
                                           unsigned h, unsigned l) {
    int kt = p >> 4, pl_ = p & 15;
    int s = pl_ >> 3, rem = pl_ & 7;
    int t4 = rem & 3, woff = (rem >> 2) * 2;
    int mb = r >> 7, rr = r & 127;
    int fm = rr >> 4, r16 = rr & 15;
    int r1f = r16 >> 3, g4 = r16 & 7;
    int f = (fm * 2 + s) * 32 + g4 * 4 + t4;
    size_t idx = ((size_t)(mb * nkt + kt)) * 2048 + f * 4 + woff + r1f;
    ph[idx] = h; pl[idx] = l;
}

// ---------------- block reductions ----------------
__device__ __forceinline__ float block_sum_256(float val, float* red) {
    #pragma unroll
    for (int o = 16; o > 0; o >>= 1) val += __shfl_xor_sync(0xffffffffu, val, o);
    if ((threadIdx.x & 31) == 0) red[threadIdx.x >> 5] = val;
    __syncthreads();
    float s = red[0];
    #pragma unroll
    for (int w = 1; w < 8; w++) s += red[w];
    __syncthreads();
    return s;
}
__device__ __forceinline__ float block_max_128(float val, float* red) {
    #pragma unroll
    for (int o = 16; o > 0; o >>= 1) val = fmaxf(val, __shfl_xor_sync(0xffffffffu, val, o));
    if ((threadIdx.x & 31) == 0) red[threadIdx.x >> 5] = val;
    __syncthreads();
    float m = fmaxf(fmaxf(red[0], red[1]), fmaxf(red[2], red[3]));
    __syncthreads();
    return m;
}
__device__ __forceinline__ float block_sum_128(float val, float* red) {
    #pragma unroll
    for (int o = 16; o > 0; o >>= 1) val += __shfl_xor_sync(0xffffffffu, val, o);
    if ((threadIdx.x & 31) == 0) red[threadIdx.x >> 5] = val;
    __syncthreads();
    float s = red[0] + red[1] + red[2] + red[3];
    __syncthreads();
    return s;
}

// ============ weight prepack: fp32 [K,N] -> fragment-major split-bf16 tiles ========
__global__ void prepack_kernel(const float* __restrict__ W,
                               __nv_bfloat16* __restrict__ hi,
                               __nv_bfloat16* __restrict__ lo, int N)
{
    __shared__ float ws[32][132];
    int kb = blockIdx.x, nb = blockIdx.y;
    int tid = threadIdx.x;
    int k0 = kb * 32, n0 = nb * 128;
    #pragma unroll
    for (int i = 0; i < 4; i++) {
        int idx = tid + i * 256;
        int row = idx >> 5, c4 = (idx & 31) * 4;
        float4 v = *(const float4*)(W + (size_t)(k0 + row) * N + n0 + c4);
        ws[row][c4] = v.x; ws[row][c4 + 1] = v.y;
        ws[row][c4 + 2] = v.z; ws[row][c4 + 3] = v.w;
    }
    __syncthreads();
    size_t tb = ((size_t)nb * gridDim.x + kb) * 4096;
    uint2* dh = (uint2*)(hi + tb);
    uint2* dl = (uint2*)(lo + tb);
    #pragma unroll
    for (int i = 0; i < 4; i++) {
        int f = tid + i * 256;
        int lane = f & 31, s = (f >> 5) & 1, fn = f >> 6;
        int c = (fn >> 2) * 32 + (fn & 3) * 8 + (lane >> 2);
        int t4 = lane & 3;
        int p0 = s * 8 + t4, p1 = p0 + 4;
        unsigned h0, l0, h1, l1;
        bsplit(ws[2 * p0][c], ws[2 * p0 + 1][c], h0, l0);
        bsplit(ws[2 * p1][c], ws[2 * p1 + 1][c], h1, l1);
        dh[f] = make_uint2(h0, h1);
        dl[f] = make_uint2(l0, l1);
    }
}

// concat per-layer QKV biases into [L, 2304]
__global__ void biascat_kernel(const float* __restrict__ bq, const float* __restrict__ bk,
                               const float* __restrict__ bv, float* __restrict__ o)
{
    int l = blockIdx.x, t = threadIdx.x;
    #pragma unroll
    for (int i = 0; i < 3; i++) {
        int c = t + i * 256;
        o[(size_t)l * 2304 + c]        = bq[(size_t)l * Hsz + c];
        o[(size_t)l * 2304 + 768 + c]  = bk[(size_t)l * Hsz + c];
        o[(size_t)l * 2304 + 1536 + c] = bv[(size_t)l * Hsz + c];
    }
}

// ======== weight GEMM: C = A @ W + bias (split-bf16 3-pass, cp.async pipeline) =====
// A,B prepacked fragment-major in gmem. 128x128x32 tiles, 4 warps (64x64 warp tile),
// 3-stage pipeline 96KB. MODE 0: row-major out. MODE 2: fused QKV scatter.
// MODE 5: gelu, write A-fragment planes directly (ldc = Ntot/32 tile pitch).
template <int MODE>
__global__ void __launch_bounds__(128)
wgemm(const __nv_bfloat16* __restrict__ Ahi, const __nv_bfloat16* __restrict__ Alo,
      const __nv_bfloat16* __restrict__ Bhi, const __nv_bfloat16* __restrict__ Blo,
      const float* __restrict__ bias, float* __restrict__ C, int K, int ldc,
      __nv_bfloat16* __restrict__ Ph, __nv_bfloat16* __restrict__ Pl)
{
    extern __shared__ uint4 sm[];
    int tid = threadIdx.x, lane = tid & 31, warp = tid >> 5;
    int wmq = warp >> 1, wnq = warp & 1;          // warp tile 64x64
    int bn = blockIdx.x * 128, bm = blockIdx.y * 128;
    int nkt = K >> 5;
    uint32_t smb = (uint32_t)__cvta_generic_to_shared(sm);

    float acc[4][8][4];
    #pragma unroll
    for (int i = 0; i < 4; i++)
        #pragma unroll
        for (int j = 0; j < 8; j++)
            #pragma unroll
            for (int t = 0; t < 4; t++) acc[i][j][t] = 0.0f;

    auto ISSUE = [&](int kt) {
        int st = kt % 3;
        uint32_t d = smb + st * 32768u;
        size_t ta = ((size_t)blockIdx.y * nkt + kt) * 512;
        size_t tb = ((size_t)blockIdx.x * nkt + kt) * 512;
        const uint4* gah = (const uint4*)Ahi + ta;
        const uint4* gal = (const uint4*)Alo + ta;
        const uint4* gbh = (const uint4*)Bhi + tb;
        const uint4* gbl = (const uint4*)Blo + tb;
        #pragma unroll
        for (int i = 0; i < 4; i++) {
            int o = tid + i * 128;
            cp16(d + o * 16u,           gah + o);
            cp16(d + 8192u  + o * 16u,  gal + o);
            cp16(d + 16384u + o * 16u,  gbh + o);
            cp16(d + 24576u + o * 16u,  gbl + o);
        }
        CP_COMMIT();
    };

    ISSUE(0);
    ISSUE(1);

    for (int kt = 0; kt < nkt; kt++) {
        if (kt + 1 < nkt) asm volatile("cp.async.wait_group 1;");
        else              asm volatile("cp.async.wait_group 0;");
        __syncthreads();
        if (kt + 2 < nkt) ISSUE(kt + 2);

        const uint4* AHs = sm + (kt % 3) * 2048;
        const uint4* ALs = AHs + 512;
        const uint2* BHs = (const uint2*)(AHs + 1024);
        const uint2* BLs = (const uint2*)(AHs + 1536);
        #pragma unroll
        for (int s = 0; s < 2; s++) {
            uint4 a_h[4], a_l[4];
            uint2 b_h[8], b_l[8];
            #pragma unroll
            for (int mt = 0; mt < 4; mt++) {
                int idx = ((wmq * 4 + mt) * 2 + s) * 32 + lane;
                a_h[mt] = AHs[idx]; a_l[mt] = ALs[idx];
            }
            #pragma unroll
            for (int nt = 0; nt < 8; nt++) {
                int idx = ((wnq * 8 + nt) * 2 + s) * 32 + lane;
                b_h[nt] = BHs[idx]; b_l[nt] = BLs[idx];
            }
            #pragma unroll
            for (int mt = 0; mt < 4; mt++)
                #pragma unroll
                for (int nt = 0; nt < 8; nt++)
                    mma16816(acc[mt][nt], (const unsigned*)&a_h[mt], (const unsigned*)&b_h[nt]);
            #pragma unroll
            for (int mt = 0; mt < 4; mt++)
                #pragma unroll
                for (int nt = 0; nt < 8; nt++)
                    mma16816(acc[mt][nt], (const unsigned*)&a_l[mt], (const unsigned*)&b_h[nt]);
            #pragma unroll
            for (int mt = 0; mt < 4; mt++)
                #pragma unroll
                for (int nt = 0; nt < 8; nt++)
                    mma16816(acc[mt][nt], (const unsigned*)&a_h[mt], (const unsigned*)&b_l[nt]);
        }
    }

    // ---- epilogue ----
    int t4 = lane & 3, g4 = lane >> 2;
    int wm = wmq * 64, wn = wnq * 64;
    if (MODE == 5) {
        // warp covers 2 k-tiles (32 cols each): ktl = nt>>2, s = (nt>>1)&1
        #pragma unroll
        for (int mt = 0; mt < 4; mt++) {
            int fm = wmq * 4 + mt;
            #pragma unroll
            for (int nt = 0; nt < 8; nt += 2) {
                int ktl = nt >> 2, s = (nt >> 1) & 1;
                float* a0 = acc[mt][nt];
                float* a1 = acc[mt][nt + 1];
                int cg0 = bn + wn + ktl * 32 + s * 16 + 2 * t4;
                int cg1 = cg0 + 8;
                float v00 = gelu1(a0[0] + bias[cg0]), v01 = gelu1(a0[1] + bias[cg0 + 1]);
                float v10 = gelu1(a0[2] + bias[cg0]), v11 = gelu1(a0[3] + bias[cg0 + 1]);
                float u00 = gelu1(a1[0] + bias[cg1]), u01 = gelu1(a1[1] + bias[cg1 + 1]);
                float u10 = gelu1(a1[2] + bias[cg1]), u11 = gelu1(a1[3] + bias[cg1 + 1]);
                unsigned h0, l0, h1, l1, h2, l2, h3, l3;
                bsplit(v00, v01, h0, l0);   // (r0, p0)
                bsplit(v10, v11, h1, l1);   // (r1, p0)
                bsplit(u00, u01, h2, l2);   // (r0, p1)
                bsplit(u10, u11, h3, l3);   // (r1, p1)
                size_t tile = (size_t)blockIdx.y * ldc + blockIdx.x * 4 + wnq * 2 + ktl;
                uint4* dh = (uint4*)Ph + tile * 512;
                uint4* dl = (uint4*)Pl + tile * 512;
                int f = (fm * 2 + s) * 32 + lane;
                dh[f] = make_uint4(h0, h1, h2, h3);
                dl[f] = make_uint4(l0, l1, l2, l3);
            }
        }
        return;
    }
    #pragma unroll
    for (int mt = 0; mt < 4; mt++) {
        int rg = bm + wm + mt * 16 + g4;
        #pragma unroll
        for (int nt = 0; nt < 8; nt++) {
            int cg = bn + wn + nt * 8 + 2 * t4;
            float* a4 = acc[mt][nt];
            float b0v = bias[cg], b1v = bias[cg + 1];
            float v00 = a4[0] + b0v, v01 = a4[1] + b1v;
            float v10 = a4[2] + b0v, v11 = a4[3] + b1v;
            if (MODE == 2) {
                int mat = cg / Hsz, c2 = cg - mat * Hsz;
                int h = c2 >> 6, d = c2 & 63;
                int b_ = rg >> 9, s0 = rg & 511;
                size_t base = (size_t)mat * TOKH;
                size_t o0 = base + (((size_t)(b_ * NHsz + h) * Ssz + s0) << 6) + d;
                size_t o1 = base + (((size_t)(b_ * NHsz + h) * Ssz + s0 + 8) << 6) + d;
                *(float2*)&C[o0] = make_float2(v00, v01);
                *(float2*)&C[o1] = make_float2(v10, v11);
            } else {
                *(float2*)&C[(size_t)rg * ldc + cg]       = make_float2(v00, v01);
                *(float2*)&C[(size_t)(rg + 8) * ldc + cg] = make_float2(v10, v11);
            }
        }
    }
}

// ---------------- embeddings + LN + gaussian noise (+ x planes) ----------------
__global__ void embed_kernel(const int* __restrict__ ids, const int* __restrict__ tts,
                             const float* __restrict__ we, const float* __restrict__ pe,
                             const float* __restrict__ te, const float* __restrict__ g,
                             const float* __restrict__ beta, const float* __restrict__ imp,
                             const float* __restrict__ noise, float* __restrict__ x,
                             __nv_bfloat16* __restrict__ xh, __nv_bfloat16* __restrict__ xl)
{
    __shared__ float red[8];
    __shared__ float rowb[Hsz];
    int tok = blockIdx.x;
    int s   = tok & (Ssz - 1);
    int tid = threadIdx.x;
    long id = ids[tok];
    long tt = tts[tok];
    float v[3];
    #pragma unroll
    for (int i = 0; i < 3; i++) {
        int hh = tid + i * 256;
        v[i] = we[(size_t)id * Hsz + hh] + pe[(size_t)s * Hsz + hh] + te[(size_t)tt * Hsz + hh];
    }
    float mu = block_sum_256(v[0] + v[1] + v[2], red) * (1.0f / Hsz);
    float d0 = v[0] - mu, d1 = v[1] - mu, d2 = v[2] - mu;
    float var = block_sum_256(d0 * d0 + d1 * d1 + d2 * d2, red) * (1.0f / Hsz);
    float rstd = rsqrtf(var + 1e-12f);
    float ip = imp[tok];
    float sg = 1.0f - ip;
    bool  nz = (ip != 0.0f);
    float dd[3] = {d0, d1, d2};
    #pragma unroll
    for (int i = 0; i < 3; i++) {
        int hh = tid + i * 256;
        float e = dd[i] * rstd * g[hh] + beta[hh];
        if (nz) e = e + noise[(size_t)tok * Hsz + hh] * sg * e;
        x[(size_t)tok * Hsz + hh] = e;
        rowb[hh] = e;
    }
    __syncthreads();
    #pragma unroll
    for (int i = 0; i < 2; i++) {
        int p = tid + i * 256;
        if (p < Hsz / 2) {
            unsigned h, l;
            bsplit(rowb[2 * p], rowb[2 * p + 1], h, l);
            plane_word((unsigned*)xh, (unsigned*)xl, tok, p, Hsz / 32, h, l);
        }
    }
}

// ---------------- residual add + LayerNorm (in-place on x, + x planes) ------------
__global__ void add_ln_kernel(float* __restrict__ x, const float* __restrict__ r,
                              const float* __restrict__ g, const float* __restrict__ beta,
                              __nv_bfloat16* __restrict__ xh, __nv_bfloat16* __restrict__ xl)
{
    __shared__ float red[8];
    __shared__ float rowb[Hsz];
    int tok = blockIdx.x, tid = threadIdx.x;
    size_t base = (size_t)tok * Hsz;
    float v[3];
    #pragma unroll
    for (int i = 0; i < 3; i++) {
        int hh = tid + i * 256;
        v[i] = x[base + hh] + r[base + hh];
    }
    float mu = block_sum_256(v[0] + v[1] + v[2], red) * (1.0f / Hsz);
    float d0 = v[0] - mu, d1 = v[1] - mu, d2 = v[2] - mu;
    float var = block_sum_256(d0 * d0 + d1 * d1 + d2 * d2, red) * (1.0f / Hsz);
    float rstd = rsqrtf(var + 1e-12f);
    float dd[3] = {d0, d1, d2};
    #pragma unroll
    for (int i = 0; i < 3; i++) {
        int hh = tid + i * 256;
        float e = dd[i] * rstd * g[hh] + beta[hh];
        x[base + hh] = e;
        rowb[hh] = e;
    }
    __syncthreads();
    #pragma unroll
    for (int i = 0; i < 2; i++) {
        int p = tid + i * 256;
        if (p < Hsz / 2) {
            unsigned h, l;
            bsplit(rowb[2 * p], rowb[2 * p + 1], h, l);
            plane_word((unsigned*)xh, (unsigned*)xl, tok, p, Hsz / 32, h, l);
        }
    }
}

// ---------------- mma.sync GEMM (attention; unchanged from R11 pass) --------------
// MODE 3: scores = A@B^T * 0.125 + maskbias.
// MODE 4: ctx = P@V written as A-fragment planes (Ph/Pl), no fp32 out.
template <int MODE, bool TRANSB>
__global__ void __launch_bounds__(256)
mma_gemm(const float* __restrict__ A, const float* __restrict__ Bm,
         float* __restrict__ C, int N, int K, int lda, int ldb, int ldc,
         long long sA, long long sB, long long sC, const float* __restrict__ amask,
         __nv_bfloat16* __restrict__ Ph, __nv_bfloat16* __restrict__ Pl)
{
    __shared__ unsigned Ash[16][132];
    __shared__ unsigned Asl[16][132];
    __shared__ unsigned Bsh[16][132];
    __shared__ unsigned Bsl[16][132];

    int tid = threadIdx.x, lane = tid & 31, warp = tid >> 5;
    int wm = (warp >> 2) * 64;
    int wn = (warp & 3) * 32;
    int bm = blockIdx.y * 128, bn = blockIdx.x * 128;
    int z  = blockIdx.z;
    A  += (size_t)z * sA;
    Bm += (size_t)z * sB;
    C  += (size_t)z * sC;

    float acc[4][4][4];
    #pragma unroll
    for (int i = 0; i < 4; i++)
        #pragma unroll
        for (int j = 0; j < 4; j++)
            #pragma unroll
            for (int t = 0; t < 4; t++) acc[i][j][t] = 0.0f;

    for (int k0 = 0; k0 < K; k0 += 32) {
        {
            int m = tid >> 1, cb = (tid & 1) * 16;
            const float* Ap = A + (size_t)(bm + m) * lda + k0 + cb;
            #pragma unroll
            for (int cc = 0; cc < 16; cc += 4) {
                float4 v = *(const float4*)(Ap + cc);
                int p = (cb + cc) >> 1;
                unsigned h0, l0, h1, l1;
                bsplit(v.x, v.y, h0, l0);
                bsplit(v.z, v.w, h1, l1);
                Ash[p][m] = h0;     Asl[p][m] = l0;
                Ash[p + 1][m] = h1; Asl[p + 1][m] = l1;
            }
        }
        if (TRANSB) {
            int n = tid >> 1, cb = (tid & 1) * 16;
            const float* Bp = Bm + (size_t)(bn + n) * ldb + k0 + cb;
            #pragma unroll
            for (int cc = 0; cc < 16; cc += 4) {
                float4 v = *(const float4*)(Bp + cc);
                int p = (cb + cc) >> 1;
                unsigned h0, l0, h1, l1;
                bsplit(v.x, v.y, h0, l0);
                bsplit(v.z, v.w, h1, l1);
                Bsh[p][n] = h0;     Bsl[p][n] = l0;
                Bsh[p + 1][n] = h1; Bsl[p + 1][n] = l1;
            }
        } else {
            int qd = tid >> 5, n0 = lane * 4;
            bool valid = (bn + n0) < N;
            #pragma unroll
            for (int half = 0; half < 2; half++) {
                int kr = k0 + 2 * qd + half * 16;
                float4 r0, r1;
                if (valid) {
                    r0 = *(const float4*)(Bm + (size_t)kr * ldb + bn + n0);
                    r1 = *(const float4*)(Bm + (size_t)(kr + 1) * ldb + bn + n0);
                } else {
                    r0 = make_float4(0.f, 0.f, 0.f, 0.f);
                    r1 = r0;
                }
                uint4 Hh, Ll;
                bsplit(r0.x, r1.x, Hh.x, Ll.x);
                bsplit(r0.y, r1.y, Hh.y, Ll.y);
                bsplit(r0.z, r1.z, Hh.z, Ll.z);
                bsplit(r0.w, r1.w, Hh.w, Ll.w);
                *(uint4*)&Bsh[qd + half * 8][n0] = Hh;
                *(uint4*)&Bsl[qd + half * 8][n0] = Ll;
            }
        }
        __syncthreads();

        #pragma unroll
        for (int s = 0; s < 2; s++) {
            int pb = s * 8;
            int t4 = lane & 3, g4 = lane >> 2;
            unsigned ah[4][4], alr[4][4], bb[4][2];
            #pragma unroll
            for (int mt = 0; mt < 4; mt++) {
                int r = wm + mt * 16 + g4;
                ah[mt][0]  = Ash[pb + t4][r];     ah[mt][1]  = Ash[pb + t4][r + 8];
                ah[mt][2]  = Ash[pb + 4 + t4][r]; ah[mt][3]  = Ash[pb + 4 + t4][r + 8];
                alr[mt][0] = Asl[pb + t4][r];     alr[mt][1] = Asl[pb + t4][r + 8];
                alr[mt][2] = Asl[pb + 4 + t4][r]; alr[mt][3] = Asl[pb + 4 + t4][r + 8];
            }
            #pragma unroll
            for (int nt = 0; nt < 4; nt++) {
                int c = wn + nt * 8 + g4;
                bb[nt][0] = Bsh[pb + t4][c];
                bb[nt][1] = Bsh[pb + 4 + t4][c];
            }
            #pragma unroll
            for (int mt = 0; mt < 4; mt++)
                #pragma unroll
                for (int nt = 0; nt < 4; nt++) mma16816(acc[mt][nt], ah[mt], bb[nt]);
            #pragma unroll
            for (int mt = 0; mt < 4; mt++)
                #pragma unroll
                for (int nt = 0; nt < 4; nt++) mma16816(acc[mt][nt], alr[mt], bb[nt]);
            #pragma unroll
            for (int nt = 0; nt < 4; nt++) {
                int c = wn + nt * 8 + g4;
                bb[nt][0] = Bsl[pb + t4][c];
                bb[nt][1] = Bsl[pb + 4 + t4][c];
            }
            #pragma unroll
            for (int mt = 0; mt < 4; mt++)
                #pragma unroll
                for (int nt = 0; nt < 4; nt++) mma16816(acc[mt][nt], ah[mt], bb[nt]);
        }
        __syncthreads();
    }

    int t4 = lane & 3, g4 = lane >> 2;
    if (MODE == 4) {
        if (wn < 64) {
            int zb = z / NHsz, h = z % NHsz;
            int mb = zb * 4 + blockIdx.y;
            int kt = h * 2 + (warp & 3);
            size_t tile = (size_t)(mb * 24 + kt);
            uint4* dh = (uint4*)Ph + tile * 512;
            uint4* dl = (uint4*)Pl + tile * 512;
            #pragma unroll
            for (int mt = 0; mt < 4; mt++) {
                int fm = (warp >> 2) * 4 + mt;
                #pragma unroll
                for (int s = 0; s < 2; s++) {
                    float* a0 = acc[mt][2 * s];
                    float* a1 = acc[mt][2 * s + 1];
                    unsigned h0, l0, h1, l1, h2, l2, h3, l3;
                    bsplit(a0[0], a0[1], h0, l0);
                    bsplit(a0[2], a0[3], h1, l1);
                    bsplit(a1[0], a1[1], h2, l2);
                    bsplit(a1[2], a1[3], h3, l3);
                    int f = (fm * 2 + s) * 32 + lane;
                    dh[f] = make_uint4(h0, h1, h2, h3);
                    dl[f] = make_uint4(l0, l1, l2, l3);
                }
            }
        }
        return;
    }
    #pragma unroll
    for (int mt = 0; mt < 4; mt++) {
        int rg = bm + wm + mt * 16 + g4;
        #pragma unroll
        for (int nt = 0; nt < 4; nt++) {
            int cg = bn + wn + nt * 8 + 2 * t4;
            float* a4 = acc[mt][nt];
            int b_ = z / NHsz;
            float m0 = (amask[b_ * Ssz + cg]     - 1.0f) * 10000.0f;
            float m1 = (amask[b_ * Ssz + cg + 1] - 1.0f) * 10000.0f;
            *(float2*)&C[(size_t)rg * ldc + cg] =
                make_float2(a4[0] * 0.125f + m0, a4[1] * 0.125f + m1);
            *(float2*)&C[(size_t)(rg + 8) * ldc + cg] =
                make_float2(a4[2] * 0.125f + m0, a4[3] * 0.125f + m1);
        }
    }
}

// ---------------- row softmax over scores (mask/scale already applied) ----------
__global__ void softmax_kernel(float* __restrict__ sc)
{
    __shared__ float red[4];
    int row = blockIdx.x, z = blockIdx.y;
    float4* p = (float4*)(sc + ((size_t)z * Ssz + row) * Ssz);
    float4 v = p[threadIdx.x];
    float m = fmaxf(fmaxf(v.x, v.y), fmaxf(v.z, v.w));
    m = block_max_128(m, red);
    v.x = __expf(v.x - m); v.y = __expf(v.y - m);
    v.z = __expf(v.z - m); v.w = __expf(v.w - m);
    float s = block_sum_128(v.x + v.y + v.z + v.w, red);
    float inv = __frcp_rn(s);
    v.x *= inv; v.y *= inv; v.z *= inv; v.w *= inv;
    p[threadIdx.x] = v;
}

// ---------------- pooler ----------------
__global__ void pool_kernel(const float* __restrict__ x, const float* __restrict__ w,
                            const float* __restrict__ pb, float* __restrict__ out)
{
    int n = blockIdx.x * 128 + threadIdx.x;
    int b = blockIdx.y;
    const float* xr = x + (size_t)b * Ssz * Hsz;
    float acc = 0.0f;
    for (int kk = 0; kk < Hsz; kk++)
        acc = fmaf(xr[kk], w[(size_t)kk * Hsz + n], acc);
    out[(size_t)b * Hsz + n] = tanhf(acc + pb[n]);
}

// ---------------- launch ----------------
#define WG_SMEM (3 * 2048 * 16)   // 96 KB dynamic, 3 pipeline stages

extern "C" void kernel_launch(void* const* d_in, const int* in_sizes, int n_in,
                              void* d_out, int out_size)
{
    const int*   ids   = (const int*)d_in[0];
    const int*   tts   = (const int*)d_in[1];
    const float* amask = (const float*)d_in[2];
    const float* imp   = (const float*)d_in[3];
    const float* noise = (const float*)d_in[4];
    const float* we    = (const float*)d_in[5];
    const float* pe    = (const float*)d_in[6];
    const float* te    = (const float*)d_in[7];
    const float* eg    = (const float*)d_in[8];
    const float* ebta  = (const float*)d_in[9];
    const float* Wq    = (const float*)d_in[10];
    const float* bq    = (const float*)d_in[11];
    const float* Wk    = (const float*)d_in[12];
    const float* bk    = (const float*)d_in[13];
    const float* Wv    = (const float*)d_in[14];
    const float* bv    = (const float*)d_in[15];
    const float* Wo    = (const float*)d_in[16];
    const float* bo    = (const float*)d_in[17];
    const float* g1    = (const float*)d_in[18];
    const float* b1    = (const float*)d_in[19];
    const float* Wi    = (const float*)d_in[20];
    const float* bi    = (const float*)d_in[21];
    const float* Wd    = (const float*)d_in[22];
    const float* bd    = (const float*)d_in[23];
    const float* g2    = (const float*)d_in[24];
    const float* b2    = (const float*)d_in[25];
    const float* pw    = (const float*)d_in[26];
    const float* pb    = (const float*)d_in[27];
    float* out = (float*)d_out;

    float *x, *qkv, *tmp, *sc, *bqkv;
    __nv_bfloat16 *whi, *wlo, *xh, *xl, *ch, *cl, *fh, *fl;
    cudaGetSymbolAddress((void**)&x,    g_x);
    cudaGetSymbolAddress((void**)&qkv,  g_qkv);
    cudaGetSymbolAddress((void**)&tmp,  g_tmp);
    cudaGetSymbolAddress((void**)&sc,   g_sc);
    cudaGetSymbolAddress((void**)&bqkv, g_bqkv);
    cudaGetSymbolAddress((void**)&whi,  g_whi);
    cudaGetSymbolAddress((void**)&wlo,  g_wlo);
    cudaGetSymbolAddress((void**)&xh,   g_xh);
    cudaGetSymbolAddress((void**)&xl,   g_xl);
    cudaGetSymbolAddress((void**)&ch,   g_ch);
    cudaGetSymbolAddress((void**)&cl,   g_cl);
    cudaGetSymbolAddress((void**)&fh,   g_fh);
    cudaGetSymbolAddress((void**)&fl,   g_fl);

    cudaFuncSetAttribute(wgemm<0>, cudaFuncAttributeMaxDynamicSharedMemorySize, WG_SMEM);
    cudaFuncSetAttribute(wgemm<2>, cudaFuncAttributeMaxDynamicSharedMemorySize, WG_SMEM);
    cudaFuncSetAttribute(wgemm<5>, cudaFuncAttributeMaxDynamicSharedMemorySize, WG_SMEM);

    // ---- prepack weights + concat QKV biases ----
    for (int l = 0; l < Lsz; l++) {
        size_t lb = (size_t)l * LSTRIDE;
        prepack_kernel<<<dim3(Hsz / 32, Hsz / 128),  256>>>(Wq + (size_t)l * WHH, whi + lb,           wlo + lb,           Hsz);
        prepack_kernel<<<dim3(Hsz / 32, Hsz / 128),  256>>>(Wk + (size_t)l * WHH, whi + lb + WHH,     wlo + lb + WHH,     Hsz);
        prepack_kernel<<<dim3(Hsz / 32, Hsz / 128),  256>>>(Wv + (size_t)l * WHH, whi + lb + 2 * WHH, wlo + lb + 2 * WHH, Hsz);
        prepack_kernel<<<dim3(Hsz / 32, Hsz / 128),  256>>>(Wo + (size_t)l * WHH, whi + lb + 3 * WHH, wlo + lb + 3 * WHH, Hsz);
        prepack_kernel<<<dim3(Hsz / 32, FFsz / 128), 256>>>(Wi + (size_t)l * WHF, whi + lb + 4 * WHH, wlo + lb + 4 * WHH, FFsz);
        prepack_kernel<<<dim3(FFsz / 32, Hsz / 128), 256>>>(Wd + (size_t)l * WHF, whi + lb + 4 * WHH + WHF, wlo + lb + 4 * WHH + WHF, Hsz);
    }
    biascat_kernel<<<Lsz, 256>>>(bq, bk, bv, bqkv);

    embed_kernel<<<TOK, 256>>>(ids, tts, we, pe, te, eg, ebta, imp, noise, x, xh, xl);

    dim3 gQKV(3 * Hsz / 128, TOK / 128);          // (18, 64) fused QKV
    dim3 gHH(Hsz / 128, TOK / 128);               // (6, 64)
    dim3 gFF(FFsz / 128, TOK / 128);              // (24, 64)
    dim3 gQK(Ssz / 128, Ssz / 128, Bsz * NHsz);   // (4, 4, 192)
    dim3 gPV(1, Ssz / 128, Bsz * NHsz);           // (1, 4, 192)
    const long long bhQ = (long long)Ssz * Dsz;
    const long long bhS = (long long)Ssz * Ssz;
    float* qb = qkv;
    float* kb_ = qkv + TOKH;
    float* vb = qkv + 2 * TOKH;

    for (int l = 0; l < Lsz; l++) {
        size_t lb = (size_t)l * LSTRIDE;
        const __nv_bfloat16 *qwh = whi + lb,               *qwl = wlo + lb;      // QKV combined
        const __nv_bfloat16 *oh  = whi + lb + 3 * WHH,     *ol  = wlo + lb + 3 * WHH;
        const __nv_bfloat16 *ih  = whi + lb + 4 * WHH,     *il  = wlo + lb + 4 * WHH;
        const __nv_bfloat16 *dh  = whi + lb + 4 * WHH + WHF, *dl = wlo + lb + 4 * WHH + WHF;
        const float* bqkvl = bqkv + (size_t)l * 2304;
        const float* bol = bo + (size_t)l * Hsz;
        const float* bil = bi + (size_t)l * FFsz;
        const float* bdl = bd + (size_t)l * Hsz;
        const float* g1l = g1 + (size_t)l * Hsz;
        const float* b1l = b1 + (size_t)l * Hsz;
        const float* g2l = g2 + (size_t)l * Hsz;
        const float* b2l = b2 + (size_t)l * Hsz;

        // fused QKV (N=2304) from x planes
        wgemm<2><<<gQKV, 128, WG_SMEM>>>(xh, xl, qwh, qwl, bqkvl, qkv, Hsz, 0, nullptr, nullptr);
        mma_gemm<3, true><<<gQK, 256>>>(qb, kb_, sc, Ssz, Dsz, Dsz, Dsz, Ssz,
                                        bhQ, bhQ, bhS, amask, nullptr, nullptr);
        softmax_kernel<<<dim3(Ssz, Bsz * NHsz), 128>>>(sc);
        // PV -> ctx planes directly
        mma_gemm<4, false><<<gPV, 256>>>(sc, vb, nullptr, Dsz, Ssz, Ssz, Dsz, 0,
                                         bhS, bhQ, 0, nullptr, ch, cl);
        wgemm<0><<<gHH, 128, WG_SMEM>>>(ch, cl, oh, ol, bol, tmp, Hsz, Hsz, nullptr, nullptr);
        add_ln_kernel<<<TOK, 256>>>(x, tmp, g1l, b1l, xh, xl);
        // FFN1 -> ffn planes directly (gelu fused)
        wgemm<5><<<gFF, 128, WG_SMEM>>>(xh, xl, ih, il, bil, nullptr, Hsz, FFsz / 32, fh, fl);
        wgemm<0><<<gHH, 128, WG_SMEM>>>(fh, fl, dh, dl, bdl, tmp, FFsz, Hsz, nullptr, nullptr);
        add_ln_kernel<<<TOK, 256>>>(x, tmp, g2l, b2l, xh, xl);
    }

    cudaMemcpyAsync(out, x, (size_t)TOK * Hsz * sizeof(float),
                    cudaMemcpyDeviceToDevice);
    pool_kernel<<<dim3(Hsz / 128, Bsz), 128>>>(x, pw, pb, out + (size_t)TOK * Hsz);
}